// round 4
// baseline (speedup 1.0000x reference)
#include <cuda_runtime.h>
#include <cuda_bf16.h>
#include <mma.h>
#include <math.h>
#include <stdint.h>

using namespace nvcuda;

// ---------------------------------------------------------------------------
// Problem constants
// ---------------------------------------------------------------------------
#define BB 4
#define NN 4096
#define KK 32
#define DP 128
#define DC 69
#define NPTS (BB*NN)          // 16384
#define ALPHA 0.2f

#define AGRID 152             // 1 CTA per SM
#define NTILES 8192           // (NPTS*KK)/64 rows per tile

// attn smem layout (bytes, all 32B aligned)
#define RAW_OFF 0                 // 2 x 64x128 fp32 = 65536
#define AH_OFF  65536             // 128x136 bf16 = 34816
#define AL_OFF  100352            // 128x136 bf16 = 34816
#define NH_OFF  135168            // 64x136 bf16 = 17408
#define NL_OFF  152576            // 64x136 bf16 = 17408
#define ES_OFF  169984            // 64x132 fp32 = 33792
#define SMEM_ATTN 203776

#define LDA 136                   // bf16 padded leading dim
#define LDE 132                   // fp32 padded leading dim

__device__ float g_pooled[NPTS * DP];

#define CP_ASYNC16(dst, src) \
    asm volatile("cp.async.cg.shared.global [%0], [%1], 16;" \
        :: "r"((uint32_t)(dst)), "l"(src) : "memory")
#define CP_COMMIT() asm volatile("cp.async.commit_group;" ::: "memory")
#define CP_WAIT1()  asm volatile("cp.async.wait_group 1;" ::: "memory")
#define CP_WAIT0()  asm volatile("cp.async.wait_group 0;" ::: "memory")

__device__ __forceinline__ uint32_t smem_u32(const void* p) {
    uint32_t a;
    asm("{ .reg .u64 t; cvta.to.shared.u64 t, %1; cvt.u32.u64 %0, t; }"
        : "=r"(a) : "l"(p));
    return a;
}

// ============================================================================
// attn: e = nfn @ a via wmma bf16x3; softmax over k; pooled = sum_k att*nfn.
// 256 threads = 8 warps (4M x 2N). Tile = 64 ptk rows (2 points) x 128 d.
// ============================================================================
__global__ void __launch_bounds__(256, 1)
attn_wmma_kernel(const float* __restrict__ nfn, const float* __restrict__ a) {
    extern __shared__ char sm[];
    float* raw = (float*)(sm + RAW_OFF);                 // [2][64][128]
    __nv_bfloat16* a_h = (__nv_bfloat16*)(sm + AH_OFF);  // [128][136]
    __nv_bfloat16* a_l = (__nv_bfloat16*)(sm + AL_OFF);
    __nv_bfloat16* n_h = (__nv_bfloat16*)(sm + NH_OFF);  // [64][136]
    __nv_bfloat16* n_l = (__nv_bfloat16*)(sm + NL_OFF);
    float* e_s = (float*)(sm + ES_OFF);                  // [64][132]

    const int tid = threadIdx.x;
    const int wid = tid >> 5;
    const int bid = blockIdx.x;
    const int nt = (NTILES - bid + AGRID - 1) / AGRID;
    const uint32_t raw_smb = smem_u32(raw);

    // one-time: split a into bf16 hi/lo
    for (int idx = tid; idx < 128 * 128; idx += 256) {
        int j = idx >> 7, d = idx & 127;
        float v = a[idx];
        __nv_bfloat16 h = __float2bfloat16_rn(v);
        a_h[j * LDA + d] = h;
        a_l[j * LDA + d] = __float2bfloat16_rn(v - __bfloat162float(h));
    }

    // prefetch tile 0
    {
        const char* src = (const char*)(nfn + (size_t)bid * 8192) + tid * 16;
        uint32_t dst = raw_smb + tid * 16;
#pragma unroll
        for (int q = 0; q < 8; q++) CP_ASYNC16(dst + q * 4096, src + q * 4096);
        CP_COMMIT();
    }
    __syncthreads();

    const int wm = wid & 3;       // M block (16 ptk rows)
    const int wn = wid >> 2;      // N block (64 d cols)
    const int p = tid >> 7;       // epilogue: point within tile
    const int d = tid & 127;      // epilogue: channel

    for (int i = 0; i < nt; i++) {
        const int s = i & 1;
        // prefetch next tile into other buffer
        if (i + 1 < nt) {
            const char* src =
                (const char*)(nfn + (size_t)(bid + (size_t)(i + 1) * AGRID) * 8192) + tid * 16;
            uint32_t dst = raw_smb + ((i + 1) & 1) * 32768 + tid * 16;
#pragma unroll
            for (int q = 0; q < 8; q++) CP_ASYNC16(dst + q * 4096, src + q * 4096);
            CP_COMMIT();
            CP_WAIT1();
        } else {
            CP_WAIT0();
        }
        __syncthreads();

        // split raw(s) -> n_h / n_l
        const float* rp = raw + s * 8192;
        for (int idx = tid; idx < 64 * 128; idx += 256) {
            int r = idx >> 7, c = idx & 127;
            float v = rp[idx];
            __nv_bfloat16 h = __float2bfloat16_rn(v);
            n_h[r * LDA + c] = h;
            n_l[r * LDA + c] = __float2bfloat16_rn(v - __bfloat162float(h));
        }
        __syncthreads();

        // wmma: e[64][128] = nfn @ a  (bf16x3)
        {
            wmma::fragment<wmma::accumulator, 16, 16, 16, float> acc[4];
#pragma unroll
            for (int t = 0; t < 4; t++) wmma::fill_fragment(acc[t], 0.0f);
#pragma unroll
            for (int kk = 0; kk < 8; kk++) {
                wmma::fragment<wmma::matrix_a, 16, 16, 16, __nv_bfloat16,
                               wmma::row_major> nhf, nlf;
                wmma::load_matrix_sync(nhf, n_h + wm * 16 * LDA + kk * 16, LDA);
                wmma::load_matrix_sync(nlf, n_l + wm * 16 * LDA + kk * 16, LDA);
#pragma unroll
                for (int t = 0; t < 4; t++) {
                    wmma::fragment<wmma::matrix_b, 16, 16, 16, __nv_bfloat16,
                                   wmma::row_major> ahf, alf;
                    const int col = wn * 64 + t * 16;
                    wmma::load_matrix_sync(ahf, a_h + kk * 16 * LDA + col, LDA);
                    wmma::load_matrix_sync(alf, a_l + kk * 16 * LDA + col, LDA);
                    wmma::mma_sync(acc[t], nhf, ahf, acc[t]);
                    wmma::mma_sync(acc[t], nhf, alf, acc[t]);
                    wmma::mma_sync(acc[t], nlf, ahf, acc[t]);
                }
            }
#pragma unroll
            for (int t = 0; t < 4; t++)
                wmma::store_matrix_sync(e_s + wm * 16 * LDE + wn * 64 + t * 16,
                                        acc[t], LDE, wmma::mem_row_major);
        }
        __syncthreads();

        // epilogue: leaky_relu + softmax over k + pooled (nfn exact from raw)
        {
            float sum = 0.f, accv = 0.f;
            const float* ep = e_s + (p * 32) * LDE + d;
            const float* np = rp + (p * 32) * 128 + d;
#pragma unroll
            for (int k = 0; k < 32; k++) {
                float v = ep[k * LDE];
                v = (v > 0.f) ? v : ALPHA * v;
                float x = __expf(v);
                sum += x;
                accv += x * np[k * 128];
            }
            int pt = (bid + i * AGRID) * 2 + p;
            g_pooled[(size_t)pt * 128 + d] = __fdividef(accv, sum);
        }
        __syncthreads();
    }
}

// ============================================================================
// FFMA2 helpers (disf/out kernels, unchanged)
// ============================================================================
__device__ __forceinline__ void ffma2(unsigned long long& acc,
                                      unsigned long long a,
                                      unsigned long long b) {
    asm("fma.rn.f32x2 %0, %1, %2, %0;" : "+l"(acc) : "l"(a), "l"(b));
}
__device__ __forceinline__ unsigned long long pk(float x, float y) {
    unsigned long long r;
    asm("mov.b64 %0, {%1, %2};" : "=l"(r) : "f"(x), "f"(y));
    return r;
}
__device__ __forceinline__ float2 upk(unsigned long long v) {
    float2 r;
    asm("mov.b64 {%0, %1}, %2;" : "=f"(r.x), "=f"(r.y) : "l"(v));
    return r;
}

#define DGF_LD 72

__global__ void disf_kernel(const float* __restrict__ g,
                            const float* __restrict__ f,
                            const float* __restrict__ gn,
                            const float* __restrict__ fn,
                            const float* __restrict__ w2,
                            const float* __restrict__ b2,
                            float* __restrict__ disf) {
    extern __shared__ char sm[];
    unsigned long long* w2_s = (unsigned long long*)sm;
    float* dgf_s = (float*)(sm + 35 * 128 * 8);
    float* fn_s = dgf_s + 32 * DGF_LD;
    float* gn_s = fn_s + 32 * 64;
    float* gf_s = gn_s + 96;
    const int tid = threadIdx.x;

    for (int i = tid; i < 35 * 128; i += 128) {
        int jj = i >> 7, d = i & 127;
        float lo = w2[(2 * jj) * 128 + d];
        float hi = (2 * jj + 1 < DC) ? w2[(2 * jj + 1) * 128 + d] : 0.f;
        w2_s[i] = pk(lo, hi);
    }
    const float bias = b2[tid];
    __syncthreads();

    const int d = tid;
    const int k = tid >> 2, q = tid & 3;
    for (int pt = blockIdx.x; pt < NPTS; pt += gridDim.x) {
        const float4* fsrc = (const float4*)(fn + (size_t)pt * 2048);
#pragma unroll
        for (int i = 0; i < 4; i++)
            ((float4*)fn_s)[tid + 128 * i] = fsrc[tid + 128 * i];
        if (tid < 96) gn_s[tid] = gn[(size_t)pt * 96 + tid];
        if (tid < 64) gf_s[3 + tid] = f[(size_t)pt * 64 + tid];
        if (tid < 3) gf_s[tid] = g[(size_t)pt * 3 + tid];
        __syncthreads();

        float df2 = 0.f;
#pragma unroll
        for (int i = 0; i < 16; i++) {
            int c = q * 16 + i;
            float fv = gf_s[3 + c], fnv = fn_s[k * 64 + c];
            dgf_s[k * DGF_LD + 3 + c] = fv - fnv;
            float t = fv - 2.f * fnv;
            df2 += t * t;
        }
        df2 += __shfl_xor_sync(0xffffffffu, df2, 1);
        df2 += __shfl_xor_sync(0xffffffffu, df2, 2);
        if (q == 0) {
            float dg2 = 0.f;
#pragma unroll
            for (int c = 0; c < 3; c++) {
                float gv = gf_s[c], gnv = gn_s[k * 3 + c];
                dgf_s[k * DGF_LD + c] = gv - gnv;
                float t = gv - 2.f * gnv;
                dg2 += t * t;
            }
            dgf_s[k * DGF_LD + 67] = sqrtf(dg2);
            dgf_s[k * DGF_LD + 68] = sqrtf(df2);
        } else if (q == 1) {
            dgf_s[k * DGF_LD + 69] = 0.f;
            dgf_s[k * DGF_LD + 70] = 0.f;
            dgf_s[k * DGF_LD + 71] = 0.f;
        }
        __syncthreads();

        unsigned long long acc[32];
#pragma unroll
        for (int kk = 0; kk < 32; kk++) acc[kk] = 0ull;
#pragma unroll 1
        for (int jjp = 0; jjp < 17; jjp++) {
            unsigned long long a0 = w2_s[(2 * jjp) * 128 + d];
            unsigned long long a1 = w2_s[(2 * jjp) * 128 + 128 + d];
#pragma unroll
            for (int kk = 0; kk < 32; kk++) {
                ulonglong2 v = *(const ulonglong2*)(dgf_s + kk * DGF_LD + jjp * 4);
                ffma2(acc[kk], v.x, a0);
                ffma2(acc[kk], v.y, a1);
            }
        }
        {
            unsigned long long a0 = w2_s[34 * 128 + d];
#pragma unroll
            for (int kk = 0; kk < 32; kk++) {
                unsigned long long v =
                    *(const unsigned long long*)(dgf_s + kk * DGF_LD + 68);
                ffma2(acc[kk], v, a0);
            }
        }
        float* outp = disf + (size_t)pt * (KK * DP) + d;
#pragma unroll
        for (int kk = 0; kk < 32; kk++) {
            float2 t = upk(acc[kk]);
            outp[kk * 128] = t.x + t.y + bias;
        }
        __syncthreads();
    }
}

__global__ void out_kernel(const float* __restrict__ w1,
                           const float* __restrict__ b1,
                           float* __restrict__ out) {
    extern __shared__ char sm[];
    unsigned long long* w1_s = (unsigned long long*)sm;
    float* pr = (float*)(sm + 64 * 128 * 8);
    const int tid = threadIdx.x;

    for (int i = tid; i < 64 * 128; i += 128) {
        int dd = i >> 7, c = i & 127;
        w1_s[i] = pk(w1[(2 * dd) * 128 + c], w1[(2 * dd + 1) * 128 + c]);
    }
    const float bias = b1[tid];
    __syncthreads();

    const int c = tid;
    for (int grp = blockIdx.x; grp < NPTS / 4; grp += gridDim.x) {
#pragma unroll
        for (int i = 0; i < 4; i++)
            pr[tid + 128 * i] = g_pooled[(size_t)grp * 512 + tid + 128 * i];
        __syncthreads();

        unsigned long long acc0 = 0, acc1 = 0, acc2 = 0, acc3 = 0;
        const ulonglong2* pv = (const ulonglong2*)pr;
#pragma unroll 2
        for (int dd = 0; dd < 64; dd += 2) {
            unsigned long long a0 = w1_s[dd * 128 + c];
            unsigned long long a1 = w1_s[dd * 128 + 128 + c];
            ulonglong2 v0 = pv[0 * 32 + (dd >> 1)];
            ulonglong2 v1 = pv[1 * 32 + (dd >> 1)];
            ulonglong2 v2 = pv[2 * 32 + (dd >> 1)];
            ulonglong2 v3 = pv[3 * 32 + (dd >> 1)];
            ffma2(acc0, v0.x, a0); ffma2(acc0, v0.y, a1);
            ffma2(acc1, v1.x, a0); ffma2(acc1, v1.y, a1);
            ffma2(acc2, v2.x, a0); ffma2(acc2, v2.y, a1);
            ffma2(acc3, v3.x, a0); ffma2(acc3, v3.y, a1);
        }
        float2 t0 = upk(acc0), t1 = upk(acc1), t2 = upk(acc2), t3 = upk(acc3);
        float* o = out + (size_t)grp * 512 + c;
        o[0] = t0.x + t0.y + bias;
        o[128] = t1.x + t1.y + bias;
        o[256] = t2.x + t2.y + bias;
        o[384] = t3.x + t3.y + bias;
        __syncthreads();
    }
}

// ============================================================================
// launch
// ============================================================================
extern "C" void kernel_launch(void* const* d_in, const int* in_sizes, int n_in,
                              void* d_out, int out_size) {
    const float* g = (const float*)d_in[0];
    const float* f = (const float*)d_in[1];
    const float* gn = (const float*)d_in[2];
    const float* fn = (const float*)d_in[3];
    const float* nfn = (const float*)d_in[4];
    const float* a = (const float*)d_in[5];
    const float* w2 = (const float*)d_in[6];
    const float* b2 = (const float*)d_in[7];
    const float* w1 = (const float*)d_in[8];
    const float* b1 = (const float*)d_in[9];

    float* out = (float*)d_out;                    // [B,N,128]
    float* disf = out + (size_t)NPTS * DP;         // [B,N,K,128]

    const int smem_disf = 35 * 128 * 8 + (32 * DGF_LD + 32 * 64 + 96 + 68) * 4;
    const int smem_out = 64 * 128 * 8 + 4 * 128 * 4;

    cudaFuncSetAttribute(attn_wmma_kernel,
                         cudaFuncAttributeMaxDynamicSharedMemorySize, SMEM_ATTN);
    cudaFuncSetAttribute(disf_kernel,
                         cudaFuncAttributeMaxDynamicSharedMemorySize, smem_disf);
    cudaFuncSetAttribute(out_kernel,
                         cudaFuncAttributeMaxDynamicSharedMemorySize, smem_out);

    attn_wmma_kernel<<<AGRID, 256, SMEM_ATTN>>>(nfn, a);
    disf_kernel<<<592, 128, smem_disf>>>(g, f, gn, fn, w2, b2, disf);
    out_kernel<<<296, 128, smem_out>>>(w1, b1, out);
}

// round 5
// speedup vs baseline: 2.1475x; 2.1475x over previous
#include <cuda_runtime.h>
#include <cuda_bf16.h>
#include <mma.h>
#include <math.h>
#include <stdint.h>

using namespace nvcuda;

// ---------------------------------------------------------------------------
// Problem constants
// ---------------------------------------------------------------------------
#define BB 4
#define NN 4096
#define KK 32
#define DP 128
#define DC 69
#define NPTS (BB*NN)          // 16384
#define ALPHA 0.2f

#define GRID 152
#define NTILES 8192           // 64 ptk-rows (2 points) per tile

__device__ float g_pooled[NPTS * DP];

__device__ __forceinline__ void bf16_split(float v, __nv_bfloat16& h,
                                           __nv_bfloat16& l) {
    h = __float2bfloat16_rn(v);
    l = __float2bfloat16_rn(v - __bfloat162float(h));
}
__device__ __forceinline__ uint32_t pack2(__nv_bfloat16 a, __nv_bfloat16 b) {
    return (uint32_t)__bfloat16_as_ushort(a) |
           ((uint32_t)__bfloat16_as_ushort(b) << 16);
}
#define NAMED_BAR(id, cnt) \
    asm volatile("bar.sync %0, %1;" :: "r"(id), "r"(cnt) : "memory")

// ============================================================================
// attn: e = nfn @ a (wmma bf16x3), softmax over k, pooled.
// 512 threads = 2 independent halves of 8 warps; shared a_h/a_l.
// ============================================================================
#define A_LDA 136
#define A_LDE 132
// smem offsets (bytes)
#define AT_AH 0
#define AT_AL 34816
#define AT_HB 69632
#define AT_HSZ 68608
#define AT_NH 0
#define AT_NL 17408
#define AT_ES 34816
#define SMEM_ATTN 206848

__global__ void __launch_bounds__(512, 1)
attn_wmma_kernel(const float* __restrict__ nfn, const float* __restrict__ a) {
    extern __shared__ char sm[];
    __nv_bfloat16* a_h = (__nv_bfloat16*)(sm + AT_AH);  // [128][136]
    __nv_bfloat16* a_l = (__nv_bfloat16*)(sm + AT_AL);

    const int tid = threadIdx.x;
    const int half = tid >> 8;        // 0 or 1
    const int u = tid & 255;          // thread within half
    const int bid = blockIdx.x;

    // one-time: split a into bf16 hi/lo (all 512 threads)
    for (int idx = tid; idx < 128 * 128; idx += 512) {
        int j = idx >> 7, d = idx & 127;
        __nv_bfloat16 h, l;
        bf16_split(a[idx], h, l);
        a_h[j * A_LDA + d] = h;
        a_l[j * A_LDA + d] = l;
    }
    __syncthreads();

    char* hb = sm + AT_HB + half * AT_HSZ;
    __nv_bfloat16* n_h = (__nv_bfloat16*)(hb + AT_NH);  // [64][136]
    __nv_bfloat16* n_l = (__nv_bfloat16*)(hb + AT_NL);
    float* e_s = (float*)(hb + AT_ES);                  // [64][132]
    const int barid = 1 + half;

    const int w = u >> 5;          // warp within half
    const int wm = w & 3;
    const int wn = w >> 2;
    const int p = u >> 7;          // epilogue point
    const int d = u & 127;

    const int nt = (NTILES - bid + GRID - 1) / GRID;
    for (int j = half; j < nt; j += 2) {
        const int tile = bid + j * GRID;

        // ---- phase 1: LDG + split -> n_h/n_l ----
        const float4* gsrc = (const float4*)(nfn + (size_t)tile * 8192);
#pragma unroll
        for (int q = 0; q < 8; q++) {
            int v = u + 256 * q;            // float4 index, 2048 total
            float4 x = gsrc[v];
            __nv_bfloat16 h0, l0, h1, l1, h2, l2, h3, l3;
            bf16_split(x.x, h0, l0);
            bf16_split(x.y, h1, l1);
            bf16_split(x.z, h2, l2);
            bf16_split(x.w, h3, l3);
            int fidx = v * 4;
            int r = fidx >> 7, c = fidx & 127;
            uint2 ph = make_uint2(pack2(h0, h1), pack2(h2, h3));
            uint2 pl = make_uint2(pack2(l0, l1), pack2(l2, l3));
            *(uint2*)(n_h + r * A_LDA + c) = ph;
            *(uint2*)(n_l + r * A_LDA + c) = pl;
        }
        NAMED_BAR(barid, 256);

        // ---- phase 2: wmma bf16x3 -> e_s ----
        {
            wmma::fragment<wmma::accumulator, 16, 16, 16, float> acc[4];
#pragma unroll
            for (int t = 0; t < 4; t++) wmma::fill_fragment(acc[t], 0.0f);
#pragma unroll
            for (int kk = 0; kk < 8; kk++) {
                wmma::fragment<wmma::matrix_a, 16, 16, 16, __nv_bfloat16,
                               wmma::row_major> nhf, nlf;
                wmma::load_matrix_sync(nhf, n_h + wm * 16 * A_LDA + kk * 16, A_LDA);
                wmma::load_matrix_sync(nlf, n_l + wm * 16 * A_LDA + kk * 16, A_LDA);
#pragma unroll
                for (int t = 0; t < 4; t++) {
                    wmma::fragment<wmma::matrix_b, 16, 16, 16, __nv_bfloat16,
                                   wmma::row_major> ahf, alf;
                    const int col = wn * 64 + t * 16;
                    wmma::load_matrix_sync(ahf, a_h + kk * 16 * A_LDA + col, A_LDA);
                    wmma::load_matrix_sync(alf, a_l + kk * 16 * A_LDA + col, A_LDA);
                    wmma::mma_sync(acc[t], nhf, ahf, acc[t]);
                    wmma::mma_sync(acc[t], nhf, alf, acc[t]);
                    wmma::mma_sync(acc[t], nlf, ahf, acc[t]);
                }
            }
#pragma unroll
            for (int t = 0; t < 4; t++)
                wmma::store_matrix_sync(e_s + wm * 16 * A_LDE + wn * 64 + t * 16,
                                        acc[t], A_LDE, wmma::mem_row_major);
        }
        NAMED_BAR(barid, 256);

        // ---- phase 3: softmax + pooled (nfn = h + l) ----
        {
            float sum = 0.f, accv = 0.f;
            const float* ep = e_s + (p * 32) * A_LDE + d;
            const __nv_bfloat16* nhp = n_h + (p * 32) * A_LDA + d;
            const __nv_bfloat16* nlp = n_l + (p * 32) * A_LDA + d;
#pragma unroll
            for (int k = 0; k < 32; k++) {
                float v = ep[k * A_LDE];
                v = (v > 0.f) ? v : ALPHA * v;
                float x = __expf(v);
                sum += x;
                float nv = __bfloat162float(nhp[k * A_LDA]) +
                           __bfloat162float(nlp[k * A_LDA]);
                accv += x * nv;
            }
            g_pooled[(size_t)(tile * 2 + p) * 128 + d] = __fdividef(accv, sum);
        }
        NAMED_BAR(barid, 256);   // protect n/e before next split
    }
}

// ============================================================================
// disf: dgf = [pg|pf|dg|df] (69 ch, padded 80); disf = dgf @ w2 + b2 (wmma).
// 512 threads = 2 halves; tile = 2 points x 32 k = 64 rows.
// ============================================================================
#define D_LDW 136   // w2 smem leading dim (bf16)
#define D_LDG 88    // dgf smem leading dim (bf16)
#define D_LDE 132
// smem offsets
#define DS_W2H 0
#define DS_W2L 21760
#define DS_B2  43520
#define DS_HB  44032
#define DS_HSZ 73728
#define DS_FN  0
#define DS_F2  16384
#define DS_G2  16896
#define DS_DGH 17408
#define DS_DGL 28672
#define DS_ES  39936
#define SMEM_DISF 191488

__global__ void __launch_bounds__(512, 1)
disf_wmma_kernel(const float* __restrict__ g, const float* __restrict__ f,
                 const float* __restrict__ gn, const float* __restrict__ fn,
                 const float* __restrict__ w2, const float* __restrict__ b2,
                 float* __restrict__ disf) {
    extern __shared__ char sm[];
    __nv_bfloat16* w2h = (__nv_bfloat16*)(sm + DS_W2H);  // [80][136]
    __nv_bfloat16* w2l = (__nv_bfloat16*)(sm + DS_W2L);
    float* b2s = (float*)(sm + DS_B2);

    const int tid = threadIdx.x;
    const int half = tid >> 8;
    const int u = tid & 255;
    const int bid = blockIdx.x;

    // one-time: w2 split (rows 69..79 zero)
    for (int idx = tid; idx < 80 * 128; idx += 512) {
        int ch = idx >> 7, dd = idx & 127;
        __nv_bfloat16 h = __float2bfloat16_rn(0.f), l = h;
        if (ch < DC) bf16_split(w2[ch * 128 + dd], h, l);
        w2h[ch * D_LDW + dd] = h;
        w2l[ch * D_LDW + dd] = l;
    }
    if (tid < 128) b2s[tid] = b2[tid];
    __syncthreads();

    char* hb = sm + DS_HB + half * DS_HSZ;
    float* fn_s = (float*)(hb + DS_FN);     // [2][32][64] fp32
    float* f2 = (float*)(hb + DS_F2);       // [2][64]
    float* g2 = (float*)(hb + DS_G2);       // [2][4]
    __nv_bfloat16* dgh = (__nv_bfloat16*)(hb + DS_DGH);  // [64][88]
    __nv_bfloat16* dgl = (__nv_bfloat16*)(hb + DS_DGL);
    float* e_s = (float*)(hb + DS_ES);      // [64][132]
    const int barid = 1 + half;

    const int w = u >> 5;
    const int wm = w & 3;
    const int wn = w >> 2;
    const int r = u >> 2;       // row 0..63 (p*32 + k)
    const int q = u & 3;        // channel chunk
    const int p = r >> 5, k = r & 31;

    const int nt = (NTILES - bid + GRID - 1) / GRID;
    for (int j = half; j < nt; j += 2) {
        const int tile = bid + j * GRID;

        // ---- load fn tile (16KB coalesced) + f/g ----
        {
            const float4* src = (const float4*)(fn + (size_t)tile * 4096);
            float4* dst = (float4*)fn_s;
#pragma unroll
            for (int i = 0; i < 4; i++) dst[u + 256 * i] = src[u + 256 * i];
            if (u < 128)
                f2[u] = f[(size_t)(tile * 2 + (u >> 6)) * 64 + (u & 63)];
            if (u < 8) {
                int pp = u >> 2, c = u & 3;
                g2[pp * 4 + c] = (c < 3) ? g[(size_t)(tile * 2 + pp) * 3 + c] : 0.f;
            }
        }
        NAMED_BAR(barid, 256);

        // ---- build dgf (bf16 hi/lo) ----
        {
            float df2 = 0.f;
#pragma unroll
            for (int i = 0; i < 16; i++) {
                int c = q * 16 + i;
                float fv = f2[p * 64 + c];
                float fnv = fn_s[p * 2048 + k * 64 + c];
                float v = fv - fnv;
                __nv_bfloat16 h, l;
                bf16_split(v, h, l);
                dgh[r * D_LDG + 3 + c] = h;
                dgl[r * D_LDG + 3 + c] = l;
                float t = fv - 2.f * fnv;
                df2 += t * t;
            }
            df2 += __shfl_xor_sync(0xffffffffu, df2, 1);
            df2 += __shfl_xor_sync(0xffffffffu, df2, 2);
            if (q == 0) {
                float dg2 = 0.f;
#pragma unroll
                for (int c = 0; c < 3; c++) {
                    float gv = g2[p * 4 + c];
                    float gnv = gn[((size_t)(tile * 2 + p) * 32 + k) * 3 + c];
                    float v = gv - gnv;
                    __nv_bfloat16 h, l;
                    bf16_split(v, h, l);
                    dgh[r * D_LDG + c] = h;
                    dgl[r * D_LDG + c] = l;
                    float t = gv - 2.f * gnv;
                    dg2 += t * t;
                }
                __nv_bfloat16 h, l;
                bf16_split(sqrtf(dg2), h, l);
                dgh[r * D_LDG + 67] = h; dgl[r * D_LDG + 67] = l;
                bf16_split(sqrtf(df2), h, l);
                dgh[r * D_LDG + 68] = h; dgl[r * D_LDG + 68] = l;
            } else if (q == 1) {
                __nv_bfloat16 z = __float2bfloat16_rn(0.f);
#pragma unroll
                for (int c = 69; c < 80; c++) {
                    dgh[r * D_LDG + c] = z;
                    dgl[r * D_LDG + c] = z;
                }
            }
        }
        NAMED_BAR(barid, 256);

        // ---- wmma: e = dgf @ w2 (bf16x3, K=80) ----
        {
            wmma::fragment<wmma::accumulator, 16, 16, 16, float> acc[4];
#pragma unroll
            for (int t = 0; t < 4; t++) wmma::fill_fragment(acc[t], 0.0f);
#pragma unroll
            for (int kk = 0; kk < 5; kk++) {
                wmma::fragment<wmma::matrix_a, 16, 16, 16, __nv_bfloat16,
                               wmma::row_major> dhf, dlf;
                wmma::load_matrix_sync(dhf, dgh + wm * 16 * D_LDG + kk * 16, D_LDG);
                wmma::load_matrix_sync(dlf, dgl + wm * 16 * D_LDG + kk * 16, D_LDG);
#pragma unroll
                for (int t = 0; t < 4; t++) {
                    wmma::fragment<wmma::matrix_b, 16, 16, 16, __nv_bfloat16,
                                   wmma::row_major> whf, wlf;
                    const int col = wn * 64 + t * 16;
                    wmma::load_matrix_sync(whf, w2h + kk * 16 * D_LDW + col, D_LDW);
                    wmma::load_matrix_sync(wlf, w2l + kk * 16 * D_LDW + col, D_LDW);
                    wmma::mma_sync(acc[t], dhf, whf, acc[t]);
                    wmma::mma_sync(acc[t], dhf, wlf, acc[t]);
                    wmma::mma_sync(acc[t], dlf, whf, acc[t]);
                }
            }
#pragma unroll
            for (int t = 0; t < 4; t++)
                wmma::store_matrix_sync(e_s + wm * 16 * D_LDE + wn * 64 + t * 16,
                                        acc[t], D_LDE, wmma::mem_row_major);
        }
        NAMED_BAR(barid, 256);

        // ---- writeout: disf = e + b2, coalesced float4 ----
        {
            float* dst = disf + (size_t)tile * 64 * 128;
#pragma unroll
            for (int i = 0; i < 8; i++) {
                int v = u + 256 * i;            // float4 idx, 2048 total
                int rr = v >> 5, c4 = v & 31;
                float4 e4 = *(const float4*)(e_s + rr * D_LDE + c4 * 4);
                float4 b4 = *(const float4*)(b2s + c4 * 4);
                e4.x += b4.x; e4.y += b4.y; e4.z += b4.z; e4.w += b4.w;
                ((float4*)dst)[v] = e4;
            }
        }
        NAMED_BAR(barid, 256);
    }
}

// ============================================================================
// out = pooled @ w1 + b1 (FFMA2, unchanged)
// ============================================================================
__device__ __forceinline__ void ffma2(unsigned long long& acc,
                                      unsigned long long a,
                                      unsigned long long b) {
    asm("fma.rn.f32x2 %0, %1, %2, %0;" : "+l"(acc) : "l"(a), "l"(b));
}
__device__ __forceinline__ unsigned long long pk(float x, float y) {
    unsigned long long r;
    asm("mov.b64 %0, {%1, %2};" : "=l"(r) : "f"(x), "f"(y));
    return r;
}
__device__ __forceinline__ float2 upk(unsigned long long v) {
    float2 r;
    asm("mov.b64 {%0, %1}, %2;" : "=f"(r.x), "=f"(r.y) : "l"(v));
    return r;
}

__global__ void out_kernel(const float* __restrict__ w1,
                           const float* __restrict__ b1,
                           float* __restrict__ out) {
    extern __shared__ char sm[];
    unsigned long long* w1_s = (unsigned long long*)sm;
    float* pr = (float*)(sm + 64 * 128 * 8);
    const int tid = threadIdx.x;

    for (int i = tid; i < 64 * 128; i += 128) {
        int dd = i >> 7, c = i & 127;
        w1_s[i] = pk(w1[(2 * dd) * 128 + c], w1[(2 * dd + 1) * 128 + c]);
    }
    const float bias = b1[tid];
    __syncthreads();

    const int c = tid;
    for (int grp = blockIdx.x; grp < NPTS / 4; grp += gridDim.x) {
#pragma unroll
        for (int i = 0; i < 4; i++)
            pr[tid + 128 * i] = g_pooled[(size_t)grp * 512 + tid + 128 * i];
        __syncthreads();

        unsigned long long acc0 = 0, acc1 = 0, acc2 = 0, acc3 = 0;
        const ulonglong2* pv = (const ulonglong2*)pr;
#pragma unroll 2
        for (int dd = 0; dd < 64; dd += 2) {
            unsigned long long a0 = w1_s[dd * 128 + c];
            unsigned long long a1 = w1_s[dd * 128 + 128 + c];
            ulonglong2 v0 = pv[0 * 32 + (dd >> 1)];
            ulonglong2 v1 = pv[1 * 32 + (dd >> 1)];
            ulonglong2 v2 = pv[2 * 32 + (dd >> 1)];
            ulonglong2 v3 = pv[3 * 32 + (dd >> 1)];
            ffma2(acc0, v0.x, a0); ffma2(acc0, v0.y, a1);
            ffma2(acc1, v1.x, a0); ffma2(acc1, v1.y, a1);
            ffma2(acc2, v2.x, a0); ffma2(acc2, v2.y, a1);
            ffma2(acc3, v3.x, a0); ffma2(acc3, v3.y, a1);
        }
        float2 t0 = upk(acc0), t1 = upk(acc1), t2 = upk(acc2), t3 = upk(acc3);
        float* o = out + (size_t)grp * 512 + c;
        o[0] = t0.x + t0.y + bias;
        o[128] = t1.x + t1.y + bias;
        o[256] = t2.x + t2.y + bias;
        o[384] = t3.x + t3.y + bias;
        __syncthreads();
    }
}

// ============================================================================
// launch
// ============================================================================
extern "C" void kernel_launch(void* const* d_in, const int* in_sizes, int n_in,
                              void* d_out, int out_size) {
    const float* g = (const float*)d_in[0];
    const float* f = (const float*)d_in[1];
    const float* gn = (const float*)d_in[2];
    const float* fn = (const float*)d_in[3];
    const float* nfn = (const float*)d_in[4];
    const float* a = (const float*)d_in[5];
    const float* w2 = (const float*)d_in[6];
    const float* b2 = (const float*)d_in[7];
    const float* w1 = (const float*)d_in[8];
    const float* b1 = (const float*)d_in[9];

    float* out = (float*)d_out;                    // [B,N,128]
    float* disf = out + (size_t)NPTS * DP;         // [B,N,K,128]

    const int smem_out = 64 * 128 * 8 + 4 * 128 * 4;

    cudaFuncSetAttribute(attn_wmma_kernel,
                         cudaFuncAttributeMaxDynamicSharedMemorySize, SMEM_ATTN);
    cudaFuncSetAttribute(disf_wmma_kernel,
                         cudaFuncAttributeMaxDynamicSharedMemorySize, SMEM_DISF);
    cudaFuncSetAttribute(out_kernel,
                         cudaFuncAttributeMaxDynamicSharedMemorySize, smem_out);

    attn_wmma_kernel<<<GRID, 512, SMEM_ATTN>>>(nfn, a);
    disf_wmma_kernel<<<GRID, 512, SMEM_DISF>>>(g, f, gn, fn, w2, b2, disf);
    out_kernel<<<296, 128, smem_out>>>(w1, b1, out);
}

// round 6
// speedup vs baseline: 2.5653x; 1.1945x over previous
#include <cuda_runtime.h>
#include <cuda_bf16.h>
#include <mma.h>
#include <math.h>
#include <stdint.h>

using namespace nvcuda;

// ---------------------------------------------------------------------------
#define BB 4
#define NN 4096
#define KK 32
#define DP 128
#define DC 69
#define NPTS (BB*NN)
#define ALPHA 0.2f

#define GRID 152
#define NTILES 8192           // 64 ptk-rows (2 points) per tile

__device__ float g_pooled[NPTS * DP];

__device__ __forceinline__ void bf16_split(float v, __nv_bfloat16& h,
                                           __nv_bfloat16& l) {
    h = __float2bfloat16_rn(v);
    l = __float2bfloat16_rn(v - __bfloat162float(h));
}
__device__ __forceinline__ uint32_t pack2(__nv_bfloat16 a, __nv_bfloat16 b) {
    return (uint32_t)__bfloat16_as_ushort(a) |
           ((uint32_t)__bfloat16_as_ushort(b) << 16);
}
#define NAMED_BAR(id, cnt) \
    asm volatile("bar.sync %0, %1;" :: "r"(id), "r"(cnt) : "memory")

// ============================================================================
// attn: e = nfn @ a (wmma bf16x3, 32x32 warp tiles), softmax over k, pooled.
// 512 threads = 2 independent halves of 8 warps; shared a_h/a_l.
// ============================================================================
#define A_LDA 136
#define A_LDE 132
#define AT_AH 0
#define AT_AL 34816
#define AT_HB 69632
#define AT_HSZ 68608
#define AT_NH 0
#define AT_NL 17408
#define AT_ES 34816
#define SMEM_ATTN 206848

__global__ void __launch_bounds__(512, 1)
attn_wmma_kernel(const float* __restrict__ nfn, const float* __restrict__ a) {
    extern __shared__ char sm[];
    __nv_bfloat16* a_h = (__nv_bfloat16*)(sm + AT_AH);  // [128][136]
    __nv_bfloat16* a_l = (__nv_bfloat16*)(sm + AT_AL);

    const int tid = threadIdx.x;
    const int half = tid >> 8;
    const int u = tid & 255;
    const int bid = blockIdx.x;

    for (int idx = tid; idx < 128 * 128; idx += 512) {
        int j = idx >> 7, d = idx & 127;
        __nv_bfloat16 h, l;
        bf16_split(a[idx], h, l);
        a_h[j * A_LDA + d] = h;
        a_l[j * A_LDA + d] = l;
    }
    __syncthreads();

    char* hb = sm + AT_HB + half * AT_HSZ;
    __nv_bfloat16* n_h = (__nv_bfloat16*)(hb + AT_NH);  // [64][136]
    __nv_bfloat16* n_l = (__nv_bfloat16*)(hb + AT_NL);
    float* e_s = (float*)(hb + AT_ES);                  // [64][132]
    const int barid = 1 + half;

    const int w = u >> 5;
    const int wm = w & 1;          // 32-row block
    const int wn = w >> 1;         // 32-col block
    const int p = u >> 7;
    const int d = u & 127;

    const int nt = (NTILES - bid + GRID - 1) / GRID;
    for (int j = half; j < nt; j += 2) {
        const int tile = bid + j * GRID;

        // ---- phase 1: LDG + split -> n_h/n_l ----
        const float4* gsrc = (const float4*)(nfn + (size_t)tile * 8192);
#pragma unroll
        for (int q = 0; q < 8; q++) {
            int v = u + 256 * q;
            float4 x = gsrc[v];
            __nv_bfloat16 h0, l0, h1, l1, h2, l2, h3, l3;
            bf16_split(x.x, h0, l0);
            bf16_split(x.y, h1, l1);
            bf16_split(x.z, h2, l2);
            bf16_split(x.w, h3, l3);
            int fidx = v * 4;
            int r = fidx >> 7, c = fidx & 127;
            *(uint2*)(n_h + r * A_LDA + c) = make_uint2(pack2(h0, h1), pack2(h2, h3));
            *(uint2*)(n_l + r * A_LDA + c) = make_uint2(pack2(l0, l1), pack2(l2, l3));
        }
        NAMED_BAR(barid, 256);

        // ---- phase 2: wmma bf16x3, 32x32 per warp ----
        {
            wmma::fragment<wmma::accumulator, 16, 16, 16, float> acc[2][2];
#pragma unroll
            for (int mi = 0; mi < 2; mi++)
#pragma unroll
                for (int ni = 0; ni < 2; ni++)
                    wmma::fill_fragment(acc[mi][ni], 0.0f);
#pragma unroll
            for (int kk = 0; kk < 8; kk++) {
                wmma::fragment<wmma::matrix_a, 16, 16, 16, __nv_bfloat16,
                               wmma::row_major> nh[2], nl[2];
                wmma::fragment<wmma::matrix_b, 16, 16, 16, __nv_bfloat16,
                               wmma::row_major> ah[2], al[2];
#pragma unroll
                for (int mi = 0; mi < 2; mi++) {
                    const int row = wm * 32 + mi * 16;
                    wmma::load_matrix_sync(nh[mi], n_h + row * A_LDA + kk * 16, A_LDA);
                    wmma::load_matrix_sync(nl[mi], n_l + row * A_LDA + kk * 16, A_LDA);
                }
#pragma unroll
                for (int ni = 0; ni < 2; ni++) {
                    const int col = wn * 32 + ni * 16;
                    wmma::load_matrix_sync(ah[ni], a_h + kk * 16 * A_LDA + col, A_LDA);
                    wmma::load_matrix_sync(al[ni], a_l + kk * 16 * A_LDA + col, A_LDA);
                }
#pragma unroll
                for (int mi = 0; mi < 2; mi++)
#pragma unroll
                    for (int ni = 0; ni < 2; ni++) {
                        wmma::mma_sync(acc[mi][ni], nh[mi], ah[ni], acc[mi][ni]);
                        wmma::mma_sync(acc[mi][ni], nh[mi], al[ni], acc[mi][ni]);
                        wmma::mma_sync(acc[mi][ni], nl[mi], ah[ni], acc[mi][ni]);
                    }
            }
#pragma unroll
            for (int mi = 0; mi < 2; mi++)
#pragma unroll
                for (int ni = 0; ni < 2; ni++)
                    wmma::store_matrix_sync(
                        e_s + (wm * 32 + mi * 16) * A_LDE + wn * 32 + ni * 16,
                        acc[mi][ni], A_LDE, wmma::mem_row_major);
        }
        NAMED_BAR(barid, 256);

        // ---- phase 3: softmax + pooled (nfn = h + l) ----
        {
            float sum = 0.f, accv = 0.f;
            const float* ep = e_s + (p * 32) * A_LDE + d;
            const __nv_bfloat16* nhp = n_h + (p * 32) * A_LDA + d;
            const __nv_bfloat16* nlp = n_l + (p * 32) * A_LDA + d;
#pragma unroll
            for (int k = 0; k < 32; k++) {
                float v = ep[k * A_LDE];
                v = (v > 0.f) ? v : ALPHA * v;
                float x = __expf(v);
                sum += x;
                float nv = __bfloat162float(nhp[k * A_LDA]) +
                           __bfloat162float(nlp[k * A_LDA]);
                accv += x * nv;
            }
            g_pooled[(size_t)(tile * 2 + p) * 128 + d] = __fdividef(accv, sum);
        }
        NAMED_BAR(barid, 256);
    }
}

// ============================================================================
// disf: permuted dgf = [pf(0-63)|pg(64-66)|dg(67)|df(68)|1(69)|0(70-79)];
// disf = dgf @ w2perm (bf16x3, bias folded via ones-channel), wmma acc stored
// directly to gmem. 512 threads = 2 halves; tile = 64 rows.
// ============================================================================
#define D_LDW 136
#define D_LDG 88
#define DS_W2H 0
#define DS_W2L 21760
#define DS_HB  43520
#define DS_HSZ 22528
#define SMEM_DISF 88576

__global__ void __launch_bounds__(512, 1)
disf_wmma_kernel(const float* __restrict__ g, const float* __restrict__ f,
                 const float* __restrict__ gn, const float* __restrict__ fn,
                 const float* __restrict__ w2, const float* __restrict__ b2,
                 float* __restrict__ disf) {
    extern __shared__ char sm[];
    __nv_bfloat16* w2h = (__nv_bfloat16*)(sm + DS_W2H);  // [80][136]
    __nv_bfloat16* w2l = (__nv_bfloat16*)(sm + DS_W2L);

    const int tid = threadIdx.x;
    const int half = tid >> 8;
    const int u = tid & 255;
    const int bid = blockIdx.x;

    // one-time: permuted w2 (+bias row) split
    for (int idx = tid; idx < 80 * 128; idx += 512) {
        int ch = idx >> 7, dd = idx & 127;
        float v = 0.f;
        if (ch < 64) v = w2[(3 + ch) * 128 + dd];
        else if (ch < 67) v = w2[(ch - 64) * 128 + dd];
        else if (ch < 69) v = w2[ch * 128 + dd];
        else if (ch == 69) v = b2[dd];
        __nv_bfloat16 h, l;
        bf16_split(v, h, l);
        w2h[ch * D_LDW + dd] = h;
        w2l[ch * D_LDW + dd] = l;
    }
    __syncthreads();

    char* hb = sm + DS_HB + half * DS_HSZ;
    __nv_bfloat16* dgh = (__nv_bfloat16*)hb;             // [64][88]
    __nv_bfloat16* dgl = (__nv_bfloat16*)(hb + 11264);
    const int barid = 1 + half;

    const int w = u >> 5;
    const int wm = w & 1;
    const int wn = w >> 1;
    const int r = u >> 2;       // row 0..63
    const int q = u & 3;        // 16-channel chunk
    const int p = r >> 5;

    const int nt = (NTILES - bid + GRID - 1) / GRID;
    for (int j = half; j < nt; j += 2) {
        const int tile = bid + j * GRID;
        const int grow = tile * 64 + r;       // global (pt,k) row

        // ---- build dgf straight from LDG ----
        {
            const float4* fnp = (const float4*)(fn + (size_t)grow * 64 + q * 16);
            const float4* fp =
                (const float4*)(f + (size_t)(tile * 2 + p) * 64 + q * 16);
            float pf[16];
            float df2 = 0.f;
#pragma unroll
            for (int i = 0; i < 4; i++) {
                float4 A = fnp[i], F = fp[i];
                pf[i * 4 + 0] = F.x - A.x;
                pf[i * 4 + 1] = F.y - A.y;
                pf[i * 4 + 2] = F.z - A.z;
                pf[i * 4 + 3] = F.w - A.w;
                float t0 = F.x - 2.f * A.x, t1 = F.y - 2.f * A.y;
                float t2 = F.z - 2.f * A.z, t3 = F.w - 2.f * A.w;
                df2 += t0 * t0 + t1 * t1 + t2 * t2 + t3 * t3;
            }
            uint32_t hh[8], ll[8];
#pragma unroll
            for (int i = 0; i < 8; i++) {
                __nv_bfloat16 h0, l0, h1, l1;
                bf16_split(pf[2 * i], h0, l0);
                bf16_split(pf[2 * i + 1], h1, l1);
                hh[i] = pack2(h0, h1);
                ll[i] = pack2(l0, l1);
            }
            // 16B-aligned stores: row r at byte r*176, col q*16 -> +q*32
            uint4* dsth = (uint4*)(dgh + r * D_LDG + q * 16);
            uint4* dstl = (uint4*)(dgl + r * D_LDG + q * 16);
            dsth[0] = make_uint4(hh[0], hh[1], hh[2], hh[3]);
            dsth[1] = make_uint4(hh[4], hh[5], hh[6], hh[7]);
            dstl[0] = make_uint4(ll[0], ll[1], ll[2], ll[3]);
            dstl[1] = make_uint4(ll[4], ll[5], ll[6], ll[7]);

            df2 += __shfl_xor_sync(0xffffffffu, df2, 1);
            df2 += __shfl_xor_sync(0xffffffffu, df2, 2);

            if (q == 0) {
                // cols 64..79: pg(3), dg, df, one, zeros
                float tail[16];
#pragma unroll
                for (int i = 0; i < 16; i++) tail[i] = 0.f;
                float dg2 = 0.f;
#pragma unroll
                for (int c = 0; c < 3; c++) {
                    float gv = g[(size_t)(tile * 2 + p) * 3 + c];
                    float gnv = gn[(size_t)grow * 3 + c];
                    tail[c] = gv - gnv;
                    float t = gv - 2.f * gnv;
                    dg2 += t * t;
                }
                tail[3] = sqrtf(dg2);
                tail[4] = sqrtf(df2);
                tail[5] = 1.0f;
                uint32_t th[8], tl[8];
#pragma unroll
                for (int i = 0; i < 8; i++) {
                    __nv_bfloat16 h0, l0, h1, l1;
                    bf16_split(tail[2 * i], h0, l0);
                    bf16_split(tail[2 * i + 1], h1, l1);
                    th[i] = pack2(h0, h1);
                    tl[i] = pack2(l0, l1);
                }
                uint4* dh = (uint4*)(dgh + r * D_LDG + 64);
                uint4* dl = (uint4*)(dgl + r * D_LDG + 64);
                dh[0] = make_uint4(th[0], th[1], th[2], th[3]);
                dh[1] = make_uint4(th[4], th[5], th[6], th[7]);
                dl[0] = make_uint4(tl[0], tl[1], tl[2], tl[3]);
                dl[1] = make_uint4(tl[4], tl[5], tl[6], tl[7]);
            }
        }
        NAMED_BAR(barid, 256);

        // ---- wmma bf16x3 (K=80), store straight to gmem ----
        {
            wmma::fragment<wmma::accumulator, 16, 16, 16, float> acc[2][2];
#pragma unroll
            for (int mi = 0; mi < 2; mi++)
#pragma unroll
                for (int ni = 0; ni < 2; ni++)
                    wmma::fill_fragment(acc[mi][ni], 0.0f);
#pragma unroll
            for (int kk = 0; kk < 5; kk++) {
                wmma::fragment<wmma::matrix_a, 16, 16, 16, __nv_bfloat16,
                               wmma::row_major> dh[2], dl[2];
                wmma::fragment<wmma::matrix_b, 16, 16, 16, __nv_bfloat16,
                               wmma::row_major> wh[2], wl[2];
#pragma unroll
                for (int mi = 0; mi < 2; mi++) {
                    const int row = wm * 32 + mi * 16;
                    wmma::load_matrix_sync(dh[mi], dgh + row * D_LDG + kk * 16, D_LDG);
                    wmma::load_matrix_sync(dl[mi], dgl + row * D_LDG + kk * 16, D_LDG);
                }
#pragma unroll
                for (int ni = 0; ni < 2; ni++) {
                    const int col = wn * 32 + ni * 16;
                    wmma::load_matrix_sync(wh[ni], w2h + kk * 16 * D_LDW + col, D_LDW);
                    wmma::load_matrix_sync(wl[ni], w2l + kk * 16 * D_LDW + col, D_LDW);
                }
#pragma unroll
                for (int mi = 0; mi < 2; mi++)
#pragma unroll
                    for (int ni = 0; ni < 2; ni++) {
                        wmma::mma_sync(acc[mi][ni], dh[mi], wh[ni], acc[mi][ni]);
                        wmma::mma_sync(acc[mi][ni], dh[mi], wl[ni], acc[mi][ni]);
                        wmma::mma_sync(acc[mi][ni], dl[mi], wh[ni], acc[mi][ni]);
                    }
            }
            float* dst = disf + (size_t)tile * 64 * 128;
#pragma unroll
            for (int mi = 0; mi < 2; mi++)
#pragma unroll
                for (int ni = 0; ni < 2; ni++)
                    wmma::store_matrix_sync(
                        dst + (wm * 32 + mi * 16) * 128 + wn * 32 + ni * 16,
                        acc[mi][ni], 128, wmma::mem_row_major);
        }
        NAMED_BAR(barid, 256);
    }
}

// ============================================================================
// out = pooled @ w1 + b1 (FFMA2, unchanged)
// ============================================================================
__device__ __forceinline__ void ffma2(unsigned long long& acc,
                                      unsigned long long a,
                                      unsigned long long b) {
    asm("fma.rn.f32x2 %0, %1, %2, %0;" : "+l"(acc) : "l"(a), "l"(b));
}
__device__ __forceinline__ unsigned long long pk(float x, float y) {
    unsigned long long r;
    asm("mov.b64 %0, {%1, %2};" : "=l"(r) : "f"(x), "f"(y));
    return r;
}
__device__ __forceinline__ float2 upk(unsigned long long v) {
    float2 r;
    asm("mov.b64 {%0, %1}, %2;" : "=f"(r.x), "=f"(r.y) : "l"(v));
    return r;
}

__global__ void out_kernel(const float* __restrict__ w1,
                           const float* __restrict__ b1,
                           float* __restrict__ out) {
    extern __shared__ char sm[];
    unsigned long long* w1_s = (unsigned long long*)sm;
    float* pr = (float*)(sm + 64 * 128 * 8);
    const int tid = threadIdx.x;

    for (int i = tid; i < 64 * 128; i += 128) {
        int dd = i >> 7, c = i & 127;
        w1_s[i] = pk(w1[(2 * dd) * 128 + c], w1[(2 * dd + 1) * 128 + c]);
    }
    const float bias = b1[tid];
    __syncthreads();

    const int c = tid;
    for (int grp = blockIdx.x; grp < NPTS / 4; grp += gridDim.x) {
#pragma unroll
        for (int i = 0; i < 4; i++)
            pr[tid + 128 * i] = g_pooled[(size_t)grp * 512 + tid + 128 * i];
        __syncthreads();

        unsigned long long acc0 = 0, acc1 = 0, acc2 = 0, acc3 = 0;
        const ulonglong2* pv = (const ulonglong2*)pr;
#pragma unroll 2
        for (int dd = 0; dd < 64; dd += 2) {
            unsigned long long a0 = w1_s[dd * 128 + c];
            unsigned long long a1 = w1_s[dd * 128 + 128 + c];
            ulonglong2 v0 = pv[0 * 32 + (dd >> 1)];
            ulonglong2 v1 = pv[1 * 32 + (dd >> 1)];
            ulonglong2 v2 = pv[2 * 32 + (dd >> 1)];
            ulonglong2 v3 = pv[3 * 32 + (dd >> 1)];
            ffma2(acc0, v0.x, a0); ffma2(acc0, v0.y, a1);
            ffma2(acc1, v1.x, a0); ffma2(acc1, v1.y, a1);
            ffma2(acc2, v2.x, a0); ffma2(acc2, v2.y, a1);
            ffma2(acc3, v3.x, a0); ffma2(acc3, v3.y, a1);
        }
        float2 t0 = upk(acc0), t1 = upk(acc1), t2 = upk(acc2), t3 = upk(acc3);
        float* o = out + (size_t)grp * 512 + c;
        o[0] = t0.x + t0.y + bias;
        o[128] = t1.x + t1.y + bias;
        o[256] = t2.x + t2.y + bias;
        o[384] = t3.x + t3.y + bias;
        __syncthreads();
    }
}

// ============================================================================
// launch
// ============================================================================
extern "C" void kernel_launch(void* const* d_in, const int* in_sizes, int n_in,
                              void* d_out, int out_size) {
    const float* g = (const float*)d_in[0];
    const float* f = (const float*)d_in[1];
    const float* gn = (const float*)d_in[2];
    const float* fn = (const float*)d_in[3];
    const float* nfn = (const float*)d_in[4];
    const float* a = (const float*)d_in[5];
    const float* w2 = (const float*)d_in[6];
    const float* b2 = (const float*)d_in[7];
    const float* w1 = (const float*)d_in[8];
    const float* b1 = (const float*)d_in[9];

    float* out = (float*)d_out;                    // [B,N,128]
    float* disf = out + (size_t)NPTS * DP;         // [B,N,K,128]

    const int smem_out = 64 * 128 * 8 + 4 * 128 * 4;

    cudaFuncSetAttribute(attn_wmma_kernel,
                         cudaFuncAttributeMaxDynamicSharedMemorySize, SMEM_ATTN);
    cudaFuncSetAttribute(disf_wmma_kernel,
                         cudaFuncAttributeMaxDynamicSharedMemorySize, SMEM_DISF);
    cudaFuncSetAttribute(out_kernel,
                         cudaFuncAttributeMaxDynamicSharedMemorySize, smem_out);

    attn_wmma_kernel<<<GRID, 512, SMEM_ATTN>>>(nfn, a);
    disf_wmma_kernel<<<GRID, 512, SMEM_DISF>>>(g, f, gn, fn, w2, b2, disf);
    out_kernel<<<296, 128, smem_out>>>(w1, b1, out);
}

// round 7
// speedup vs baseline: 2.6992x; 1.0522x over previous
#include <cuda_runtime.h>
#include <cuda_bf16.h>
#include <mma.h>
#include <math.h>
#include <stdint.h>

using namespace nvcuda;

// ---------------------------------------------------------------------------
#define BB 4
#define NN 4096
#define KK 32
#define DP 128
#define DC 69
#define NPTS (BB*NN)
#define ALPHA 0.2f

#define GRID 152
#define NTILES 8192           // attn: 64 ptk-rows per tile
#define NTILES2 4096          // disf: 128 ptk-rows per tile

__device__ float g_pooled[NPTS * DP];

__device__ __forceinline__ void bf16_split(float v, __nv_bfloat16& h,
                                           __nv_bfloat16& l) {
    h = __float2bfloat16_rn(v);
    l = __float2bfloat16_rn(v - __bfloat162float(h));
}
__device__ __forceinline__ uint32_t pack2(__nv_bfloat16 a, __nv_bfloat16 b) {
    return (uint32_t)__bfloat16_as_ushort(a) |
           ((uint32_t)__bfloat16_as_ushort(b) << 16);
}
#define NAMED_BAR(id, cnt) \
    asm volatile("bar.sync %0, %1;" :: "r"(id), "r"(cnt) : "memory")

// ============================================================================
// attn (unchanged from R6): e = nfn @ a (wmma bf16x3), softmax, pooled.
// ============================================================================
#define A_LDA 136
#define A_LDE 132
#define AT_AH 0
#define AT_AL 34816
#define AT_HB 69632
#define AT_HSZ 68608
#define AT_NH 0
#define AT_NL 17408
#define AT_ES 34816
#define SMEM_ATTN 206848

__global__ void __launch_bounds__(512, 1)
attn_wmma_kernel(const float* __restrict__ nfn, const float* __restrict__ a) {
    extern __shared__ char sm[];
    __nv_bfloat16* a_h = (__nv_bfloat16*)(sm + AT_AH);
    __nv_bfloat16* a_l = (__nv_bfloat16*)(sm + AT_AL);

    const int tid = threadIdx.x;
    const int half = tid >> 8;
    const int u = tid & 255;
    const int bid = blockIdx.x;

    for (int idx = tid; idx < 128 * 128; idx += 512) {
        int j = idx >> 7, d = idx & 127;
        __nv_bfloat16 h, l;
        bf16_split(a[idx], h, l);
        a_h[j * A_LDA + d] = h;
        a_l[j * A_LDA + d] = l;
    }
    __syncthreads();

    char* hb = sm + AT_HB + half * AT_HSZ;
    __nv_bfloat16* n_h = (__nv_bfloat16*)(hb + AT_NH);
    __nv_bfloat16* n_l = (__nv_bfloat16*)(hb + AT_NL);
    float* e_s = (float*)(hb + AT_ES);
    const int barid = 1 + half;

    const int w = u >> 5;
    const int wm = w & 1;
    const int wn = w >> 1;
    const int p = u >> 7;
    const int d = u & 127;

    const int nt = (NTILES - bid + GRID - 1) / GRID;
    for (int j = half; j < nt; j += 2) {
        const int tile = bid + j * GRID;

        const float4* gsrc = (const float4*)(nfn + (size_t)tile * 8192);
#pragma unroll
        for (int q = 0; q < 8; q++) {
            int v = u + 256 * q;
            float4 x = gsrc[v];
            __nv_bfloat16 h0, l0, h1, l1, h2, l2, h3, l3;
            bf16_split(x.x, h0, l0);
            bf16_split(x.y, h1, l1);
            bf16_split(x.z, h2, l2);
            bf16_split(x.w, h3, l3);
            int fidx = v * 4;
            int r = fidx >> 7, c = fidx & 127;
            *(uint2*)(n_h + r * A_LDA + c) = make_uint2(pack2(h0, h1), pack2(h2, h3));
            *(uint2*)(n_l + r * A_LDA + c) = make_uint2(pack2(l0, l1), pack2(l2, l3));
        }
        NAMED_BAR(barid, 256);

        {
            wmma::fragment<wmma::accumulator, 16, 16, 16, float> acc[2][2];
#pragma unroll
            for (int mi = 0; mi < 2; mi++)
#pragma unroll
                for (int ni = 0; ni < 2; ni++)
                    wmma::fill_fragment(acc[mi][ni], 0.0f);
#pragma unroll
            for (int kk = 0; kk < 8; kk++) {
                wmma::fragment<wmma::matrix_a, 16, 16, 16, __nv_bfloat16,
                               wmma::row_major> nh[2], nl[2];
                wmma::fragment<wmma::matrix_b, 16, 16, 16, __nv_bfloat16,
                               wmma::row_major> ah[2], al[2];
#pragma unroll
                for (int mi = 0; mi < 2; mi++) {
                    const int row = wm * 32 + mi * 16;
                    wmma::load_matrix_sync(nh[mi], n_h + row * A_LDA + kk * 16, A_LDA);
                    wmma::load_matrix_sync(nl[mi], n_l + row * A_LDA + kk * 16, A_LDA);
                }
#pragma unroll
                for (int ni = 0; ni < 2; ni++) {
                    const int col = wn * 32 + ni * 16;
                    wmma::load_matrix_sync(ah[ni], a_h + kk * 16 * A_LDA + col, A_LDA);
                    wmma::load_matrix_sync(al[ni], a_l + kk * 16 * A_LDA + col, A_LDA);
                }
#pragma unroll
                for (int mi = 0; mi < 2; mi++)
#pragma unroll
                    for (int ni = 0; ni < 2; ni++) {
                        wmma::mma_sync(acc[mi][ni], nh[mi], ah[ni], acc[mi][ni]);
                        wmma::mma_sync(acc[mi][ni], nh[mi], al[ni], acc[mi][ni]);
                        wmma::mma_sync(acc[mi][ni], nl[mi], ah[ni], acc[mi][ni]);
                    }
            }
#pragma unroll
            for (int mi = 0; mi < 2; mi++)
#pragma unroll
                for (int ni = 0; ni < 2; ni++)
                    wmma::store_matrix_sync(
                        e_s + (wm * 32 + mi * 16) * A_LDE + wn * 32 + ni * 16,
                        acc[mi][ni], A_LDE, wmma::mem_row_major);
        }
        NAMED_BAR(barid, 256);

        {
            float sum = 0.f, accv = 0.f;
            const float* ep = e_s + (p * 32) * A_LDE + d;
            const __nv_bfloat16* nhp = n_h + (p * 32) * A_LDA + d;
            const __nv_bfloat16* nlp = n_l + (p * 32) * A_LDA + d;
#pragma unroll
            for (int k = 0; k < 32; k++) {
                float v = ep[k * A_LDE];
                v = (v > 0.f) ? v : ALPHA * v;
                float x = __expf(v);
                sum += x;
                float nv = __bfloat162float(nhp[k * A_LDA]) +
                           __bfloat162float(nlp[k * A_LDA]);
                accv += x * nv;
            }
            g_pooled[(size_t)(tile * 2 + p) * 128 + d] = __fdividef(accv, sum);
        }
        NAMED_BAR(barid, 256);
    }
}

// ============================================================================
// disf: permuted dgf (pf|pg|dg|df|1|0-pad, bias folded); 128-row tiles.
// 512 threads = 2 halves of 8 warps; warp tiles 32x64.
// ============================================================================
#define D_LDW 136
#define D_LDG 88
#define DS_W2H 0
#define DS_W2L 21760
#define DS_HB  43520
#define DS_HSZ 45056
#define SMEM_DISF 133632

__global__ void __launch_bounds__(512, 1)
disf_wmma_kernel(const float* __restrict__ g, const float* __restrict__ f,
                 const float* __restrict__ gn, const float* __restrict__ fn,
                 const float* __restrict__ w2, const float* __restrict__ b2,
                 float* __restrict__ disf) {
    extern __shared__ char sm[];
    __nv_bfloat16* w2h = (__nv_bfloat16*)(sm + DS_W2H);  // [80][136]
    __nv_bfloat16* w2l = (__nv_bfloat16*)(sm + DS_W2L);

    const int tid = threadIdx.x;
    const int half = tid >> 8;
    const int u = tid & 255;
    const int bid = blockIdx.x;

    // one-time: permuted w2 (+bias row) split
    for (int idx = tid; idx < 80 * 128; idx += 512) {
        int ch = idx >> 7, dd = idx & 127;
        float v = 0.f;
        if (ch < 64) v = w2[(3 + ch) * 128 + dd];
        else if (ch < 67) v = w2[(ch - 64) * 128 + dd];
        else if (ch < 69) v = w2[ch * 128 + dd];
        else if (ch == 69) v = b2[dd];
        __nv_bfloat16 h, l;
        bf16_split(v, h, l);
        w2h[ch * D_LDW + dd] = h;
        w2l[ch * D_LDW + dd] = l;
    }
    __syncthreads();

    char* hb = sm + DS_HB + half * DS_HSZ;
    __nv_bfloat16* dgh = (__nv_bfloat16*)hb;             // [128][88]
    __nv_bfloat16* dgl = (__nv_bfloat16*)(hb + 22528);
    const int barid = 1 + half;

    const int w = u >> 5;
    const int wm = w & 3;          // 32-row block
    const int wn = w >> 2;         // 64-col block
    const int r = u >> 1;          // row 0..127
    const int q = u & 1;           // 32-channel chunk
    const int p = r >> 5;          // point within tile (0..3)

    const int nt = (NTILES2 - bid + GRID - 1) / GRID;
    for (int j = half; j < nt; j += 2) {
        const int tile = bid + j * GRID;
        const int grow = tile * 128 + r;

        // ---- build dgf straight from LDG (32 channels per thread) ----
        {
            const float4* fnp = (const float4*)(fn + (size_t)grow * 64 + q * 32);
            const float4* fp =
                (const float4*)(f + (size_t)(tile * 4 + p) * 64 + q * 32);
            float pf[32];
            float df2 = 0.f;
#pragma unroll
            for (int i = 0; i < 8; i++) {
                float4 A = fnp[i], F = fp[i];
                pf[i * 4 + 0] = F.x - A.x;
                pf[i * 4 + 1] = F.y - A.y;
                pf[i * 4 + 2] = F.z - A.z;
                pf[i * 4 + 3] = F.w - A.w;
                float t0 = F.x - 2.f * A.x, t1 = F.y - 2.f * A.y;
                float t2 = F.z - 2.f * A.z, t3 = F.w - 2.f * A.w;
                df2 += t0 * t0 + t1 * t1 + t2 * t2 + t3 * t3;
            }
            uint4* dsth = (uint4*)(dgh + r * D_LDG + q * 32);
            uint4* dstl = (uint4*)(dgl + r * D_LDG + q * 32);
#pragma unroll
            for (int b = 0; b < 4; b++) {
                uint32_t hh[4], ll[4];
#pragma unroll
                for (int i = 0; i < 4; i++) {
                    __nv_bfloat16 h0, l0, h1, l1;
                    bf16_split(pf[b * 8 + 2 * i], h0, l0);
                    bf16_split(pf[b * 8 + 2 * i + 1], h1, l1);
                    hh[i] = pack2(h0, h1);
                    ll[i] = pack2(l0, l1);
                }
                dsth[b] = make_uint4(hh[0], hh[1], hh[2], hh[3]);
                dstl[b] = make_uint4(ll[0], ll[1], ll[2], ll[3]);
            }

            df2 += __shfl_xor_sync(0xffffffffu, df2, 1);

            if (q == 0) {
                float tail[16];
#pragma unroll
                for (int i = 0; i < 16; i++) tail[i] = 0.f;
                float dg2 = 0.f;
#pragma unroll
                for (int c = 0; c < 3; c++) {
                    float gv = g[(size_t)(tile * 4 + p) * 3 + c];
                    float gnv = gn[(size_t)grow * 3 + c];
                    tail[c] = gv - gnv;
                    float t = gv - 2.f * gnv;
                    dg2 += t * t;
                }
                tail[3] = sqrtf(dg2);
                tail[4] = sqrtf(df2);
                tail[5] = 1.0f;
                uint32_t th[8], tl[8];
#pragma unroll
                for (int i = 0; i < 8; i++) {
                    __nv_bfloat16 h0, l0, h1, l1;
                    bf16_split(tail[2 * i], h0, l0);
                    bf16_split(tail[2 * i + 1], h1, l1);
                    th[i] = pack2(h0, h1);
                    tl[i] = pack2(l0, l1);
                }
                uint4* dh = (uint4*)(dgh + r * D_LDG + 64);
                uint4* dl = (uint4*)(dgl + r * D_LDG + 64);
                dh[0] = make_uint4(th[0], th[1], th[2], th[3]);
                dh[1] = make_uint4(th[4], th[5], th[6], th[7]);
                dl[0] = make_uint4(tl[0], tl[1], tl[2], tl[3]);
                dl[1] = make_uint4(tl[4], tl[5], tl[6], tl[7]);
            }
        }
        NAMED_BAR(barid, 256);

        // ---- wmma bf16x3 (K=80), warp tile 32x64, store straight to gmem ----
        {
            wmma::fragment<wmma::accumulator, 16, 16, 16, float> acc[2][4];
#pragma unroll
            for (int mi = 0; mi < 2; mi++)
#pragma unroll
                for (int ni = 0; ni < 4; ni++)
                    wmma::fill_fragment(acc[mi][ni], 0.0f);
#pragma unroll
            for (int kk = 0; kk < 5; kk++) {
                wmma::fragment<wmma::matrix_a, 16, 16, 16, __nv_bfloat16,
                               wmma::row_major> dh[2], dl[2];
#pragma unroll
                for (int mi = 0; mi < 2; mi++) {
                    const int row = wm * 32 + mi * 16;
                    wmma::load_matrix_sync(dh[mi], dgh + row * D_LDG + kk * 16, D_LDG);
                    wmma::load_matrix_sync(dl[mi], dgl + row * D_LDG + kk * 16, D_LDG);
                }
#pragma unroll
                for (int ni = 0; ni < 4; ni++) {
                    wmma::fragment<wmma::matrix_b, 16, 16, 16, __nv_bfloat16,
                                   wmma::row_major> wh, wl;
                    const int col = wn * 64 + ni * 16;
                    wmma::load_matrix_sync(wh, w2h + kk * 16 * D_LDW + col, D_LDW);
                    wmma::load_matrix_sync(wl, w2l + kk * 16 * D_LDW + col, D_LDW);
#pragma unroll
                    for (int mi = 0; mi < 2; mi++) {
                        wmma::mma_sync(acc[mi][ni], dh[mi], wh, acc[mi][ni]);
                        wmma::mma_sync(acc[mi][ni], dh[mi], wl, acc[mi][ni]);
                        wmma::mma_sync(acc[mi][ni], dl[mi], wh, acc[mi][ni]);
                    }
                }
            }
            float* dst = disf + (size_t)tile * 128 * 128;
#pragma unroll
            for (int mi = 0; mi < 2; mi++)
#pragma unroll
                for (int ni = 0; ni < 4; ni++)
                    wmma::store_matrix_sync(
                        dst + (wm * 32 + mi * 16) * 128 + wn * 64 + ni * 16,
                        acc[mi][ni], 128, wmma::mem_row_major);
        }
        NAMED_BAR(barid, 256);
    }
}

// ============================================================================
// out = pooled @ w1 + b1 via wmma bf16x3; 64-row tiles, 256 threads.
// ============================================================================
#define O_LDW 136
#define O_LDE 132
#define OT_WH 0
#define OT_WL 34816
#define OT_B1 69632
#define OT_PH 70144
#define OT_PL 87552
#define OT_ES 104960
#define SMEM_OUT 138752

__global__ void __launch_bounds__(256, 1)
out_wmma_kernel(const float* __restrict__ w1, const float* __restrict__ b1,
                float* __restrict__ out) {
    extern __shared__ char sm[];
    __nv_bfloat16* w1h = (__nv_bfloat16*)(sm + OT_WH);   // [128][136]
    __nv_bfloat16* w1l = (__nv_bfloat16*)(sm + OT_WL);
    float* b1s = (float*)(sm + OT_B1);
    __nv_bfloat16* p_h = (__nv_bfloat16*)(sm + OT_PH);   // [64][136]
    __nv_bfloat16* p_l = (__nv_bfloat16*)(sm + OT_PL);
    float* e_s = (float*)(sm + OT_ES);                   // [64][132]

    const int tid = threadIdx.x;
    const int w = tid >> 5;
    const int wm = w & 1;
    const int wn = w >> 1;

    for (int idx = tid; idx < 128 * 128; idx += 256) {
        int j = idx >> 7, d = idx & 127;
        __nv_bfloat16 h, l;
        bf16_split(w1[idx], h, l);
        w1h[j * O_LDW + d] = h;
        w1l[j * O_LDW + d] = l;
    }
    if (tid < 128) b1s[tid] = b1[tid];
    __syncthreads();

    for (int tile = blockIdx.x; tile < NPTS / 64; tile += GRID) {
        const float4* gsrc = (const float4*)(g_pooled + (size_t)tile * 8192);
#pragma unroll
        for (int q = 0; q < 8; q++) {
            int v = tid + 256 * q;
            float4 x = gsrc[v];
            __nv_bfloat16 h0, l0, h1, l1, h2, l2, h3, l3;
            bf16_split(x.x, h0, l0);
            bf16_split(x.y, h1, l1);
            bf16_split(x.z, h2, l2);
            bf16_split(x.w, h3, l3);
            int fidx = v * 4;
            int r = fidx >> 7, c = fidx & 127;
            *(uint2*)(p_h + r * O_LDW + c) = make_uint2(pack2(h0, h1), pack2(h2, h3));
            *(uint2*)(p_l + r * O_LDW + c) = make_uint2(pack2(l0, l1), pack2(l2, l3));
        }
        __syncthreads();

        {
            wmma::fragment<wmma::accumulator, 16, 16, 16, float> acc[2][2];
#pragma unroll
            for (int mi = 0; mi < 2; mi++)
#pragma unroll
                for (int ni = 0; ni < 2; ni++)
                    wmma::fill_fragment(acc[mi][ni], 0.0f);
#pragma unroll
            for (int kk = 0; kk < 8; kk++) {
                wmma::fragment<wmma::matrix_a, 16, 16, 16, __nv_bfloat16,
                               wmma::row_major> ph[2], pl[2];
                wmma::fragment<wmma::matrix_b, 16, 16, 16, __nv_bfloat16,
                               wmma::row_major> wh[2], wl[2];
#pragma unroll
                for (int mi = 0; mi < 2; mi++) {
                    const int row = wm * 32 + mi * 16;
                    wmma::load_matrix_sync(ph[mi], p_h + row * O_LDW + kk * 16, O_LDW);
                    wmma::load_matrix_sync(pl[mi], p_l + row * O_LDW + kk * 16, O_LDW);
                }
#pragma unroll
                for (int ni = 0; ni < 2; ni++) {
                    const int col = wn * 32 + ni * 16;
                    wmma::load_matrix_sync(wh[ni], w1h + kk * 16 * O_LDW + col, O_LDW);
                    wmma::load_matrix_sync(wl[ni], w1l + kk * 16 * O_LDW + col, O_LDW);
                }
#pragma unroll
                for (int mi = 0; mi < 2; mi++)
#pragma unroll
                    for (int ni = 0; ni < 2; ni++) {
                        wmma::mma_sync(acc[mi][ni], ph[mi], wh[ni], acc[mi][ni]);
                        wmma::mma_sync(acc[mi][ni], ph[mi], wl[ni], acc[mi][ni]);
                        wmma::mma_sync(acc[mi][ni], pl[mi], wh[ni], acc[mi][ni]);
                    }
            }
#pragma unroll
            for (int mi = 0; mi < 2; mi++)
#pragma unroll
                for (int ni = 0; ni < 2; ni++)
                    wmma::store_matrix_sync(
                        e_s + (wm * 32 + mi * 16) * O_LDE + wn * 32 + ni * 16,
                        acc[mi][ni], O_LDE, wmma::mem_row_major);
        }
        __syncthreads();

        {
            float* dst = out + (size_t)tile * 8192;
#pragma unroll
            for (int i = 0; i < 8; i++) {
                int v = tid + 256 * i;
                int rr = v >> 5, c4 = v & 31;
                float4 e4 = *(const float4*)(e_s + rr * O_LDE + c4 * 4);
                float4 b4 = *(const float4*)(b1s + c4 * 4);
                e4.x += b4.x; e4.y += b4.y; e4.z += b4.z; e4.w += b4.w;
                ((float4*)dst)[v] = e4;
            }
        }
        __syncthreads();
    }
}

// ============================================================================
// launch
// ============================================================================
extern "C" void kernel_launch(void* const* d_in, const int* in_sizes, int n_in,
                              void* d_out, int out_size) {
    const float* g = (const float*)d_in[0];
    const float* f = (const float*)d_in[1];
    const float* gn = (const float*)d_in[2];
    const float* fn = (const float*)d_in[3];
    const float* nfn = (const float*)d_in[4];
    const float* a = (const float*)d_in[5];
    const float* w2 = (const float*)d_in[6];
    const float* b2 = (const float*)d_in[7];
    const float* w1 = (const float*)d_in[8];
    const float* b1 = (const float*)d_in[9];

    float* out = (float*)d_out;
    float* disf = out + (size_t)NPTS * DP;

    cudaFuncSetAttribute(attn_wmma_kernel,
                         cudaFuncAttributeMaxDynamicSharedMemorySize, SMEM_ATTN);
    cudaFuncSetAttribute(disf_wmma_kernel,
                         cudaFuncAttributeMaxDynamicSharedMemorySize, SMEM_DISF);
    cudaFuncSetAttribute(out_wmma_kernel,
                         cudaFuncAttributeMaxDynamicSharedMemorySize, SMEM_OUT);

    attn_wmma_kernel<<<GRID, 512, SMEM_ATTN>>>(nfn, a);
    disf_wmma_kernel<<<GRID, 512, SMEM_DISF>>>(g, f, gn, fn, w2, b2, disf);
    out_wmma_kernel<<<GRID, 256, SMEM_OUT>>>(w1, b1, out);
}

// round 9
// speedup vs baseline: 3.0484x; 1.1294x over previous
#include <cuda_runtime.h>
#include <cuda_bf16.h>
#include <mma.h>
#include <math.h>
#include <stdint.h>

using namespace nvcuda;

// ---------------------------------------------------------------------------
#define BB 4
#define NN 4096
#define KK 32
#define DP 128
#define DC 69
#define NPTS (BB*NN)
#define ALPHA 0.2f

#define GRID 152
#define NTILES 8192           // attn: 64 ptk-rows per tile
#define NTILES2 4096          // disf: 128 ptk-rows per tile

__device__ float g_pooled[NPTS * DP];

__device__ __forceinline__ void bf16_split(float v, __nv_bfloat16& h,
                                           __nv_bfloat16& l) {
    h = __float2bfloat16_rn(v);
    l = __float2bfloat16_rn(v - __bfloat162float(h));
}
__device__ __forceinline__ uint32_t pack2(__nv_bfloat16 a, __nv_bfloat16 b) {
    return (uint32_t)__bfloat16_as_ushort(a) |
           ((uint32_t)__bfloat16_as_ushort(b) << 16);
}
__device__ __forceinline__ float2 upk_bf2(uint32_t v) {
    __nv_bfloat162 b = *(__nv_bfloat162*)&v;
    return make_float2(__bfloat162float(b.x), __bfloat162float(b.y));
}
__device__ __forceinline__ uint32_t smem_u32(const void* p) {
    uint32_t a;
    asm("{ .reg .u64 t; cvta.to.shared.u64 t, %1; cvt.u32.u64 %0, t; }"
        : "=r"(a) : "l"(p));
    return a;
}
#define NAMED_BAR(id, cnt) \
    asm volatile("bar.sync %0, %1;" :: "r"(id), "r"(cnt) : "memory")

__device__ __forceinline__ void ldsm4(uint32_t* r, uint32_t addr) {
    asm volatile("ldmatrix.sync.aligned.m8n8.x4.shared.b16 {%0,%1,%2,%3}, [%4];"
        : "=r"(r[0]), "=r"(r[1]), "=r"(r[2]), "=r"(r[3]) : "r"(addr));
}
__device__ __forceinline__ void ldsm4t(uint32_t* r, uint32_t addr) {
    asm volatile("ldmatrix.sync.aligned.m8n8.x4.trans.shared.b16 {%0,%1,%2,%3}, [%4];"
        : "=r"(r[0]), "=r"(r[1]), "=r"(r[2]), "=r"(r[3]) : "r"(addr));
}
__device__ __forceinline__ void mma16816(float* d, const uint32_t* a,
                                         const uint32_t* b) {
    asm volatile("mma.sync.aligned.m16n8k16.row.col.f32.bf16.bf16.f32 "
        "{%0,%1,%2,%3}, {%4,%5,%6,%7}, {%8,%9}, {%0,%1,%2,%3};"
        : "+f"(d[0]), "+f"(d[1]), "+f"(d[2]), "+f"(d[3])
        : "r"(a[0]), "r"(a[1]), "r"(a[2]), "r"(a[3]), "r"(b[0]), "r"(b[1]));
}

// ============================================================================
// attn: e = nfn @ a (mma.sync bf16x3), fragment-resident softmax, pooled.
// 512 threads = 2 halves of 8 warps; shared a_h/a_l.
// ============================================================================
#define A_LDA 136
#define AT_AH 0
#define AT_AL 34816
#define AT_HB 69632
#define AT_HSZ 34816
#define AT_NH 0
#define AT_NL 17408
#define SMEM_ATTN 139264

__global__ void __launch_bounds__(512, 1)
attn_mma_kernel(const float* __restrict__ nfn, const float* __restrict__ a) {
    extern __shared__ char sm[];
    __nv_bfloat16* a_h = (__nv_bfloat16*)(sm + AT_AH);  // [128][136]
    __nv_bfloat16* a_l = (__nv_bfloat16*)(sm + AT_AL);

    const int tid = threadIdx.x;
    const int half = tid >> 8;
    const int u = tid & 255;
    const int bid = blockIdx.x;

    for (int idx = tid; idx < 128 * 128; idx += 512) {
        int j = idx >> 7, d = idx & 127;
        __nv_bfloat16 h, l;
        bf16_split(a[idx], h, l);
        a_h[j * A_LDA + d] = h;
        a_l[j * A_LDA + d] = l;
    }
    __syncthreads();

    char* hb = sm + AT_HB + half * AT_HSZ;
    __nv_bfloat16* n_h = (__nv_bfloat16*)(hb + AT_NH);  // [64][136]
    __nv_bfloat16* n_l = (__nv_bfloat16*)(hb + AT_NL);
    const int barid = 1 + half;

    const int w = u >> 5;
    const int lane = u & 31;
    const int wm = w & 1;          // point within tile (32 rows)
    const int wn = w >> 1;         // 32-col block
    const int qrow = lane >> 2;    // 0..7
    const int qc = (lane & 3) << 1;

    // ldmatrix lane-address components (same formula for A and B)
    const int lrow = lane & 15;
    const int lcol = (lane >> 4) << 3;
    const uint32_t nh_smb = smem_u32(n_h);
    const uint32_t nl_smb = smem_u32(n_l);
    const uint32_t ah_smb = smem_u32(a_h);
    const uint32_t al_smb = smem_u32(a_l);

    const int nt = (NTILES - bid + GRID - 1) / GRID;
    for (int j = half; j < nt; j += 2) {
        const int tile = bid + j * GRID;

        // ---- phase 1: LDG + split -> n_h/n_l ----
        const float4* gsrc = (const float4*)(nfn + (size_t)tile * 8192);
#pragma unroll
        for (int q = 0; q < 8; q++) {
            int v = u + 256 * q;
            float4 x = gsrc[v];
            __nv_bfloat16 h0, l0, h1, l1, h2, l2, h3, l3;
            bf16_split(x.x, h0, l0);
            bf16_split(x.y, h1, l1);
            bf16_split(x.z, h2, l2);
            bf16_split(x.w, h3, l3);
            int fidx = v * 4;
            int r = fidx >> 7, c = fidx & 127;
            *(uint2*)(n_h + r * A_LDA + c) = make_uint2(pack2(h0, h1), pack2(h2, h3));
            *(uint2*)(n_l + r * A_LDA + c) = make_uint2(pack2(l0, l1), pack2(l2, l3));
        }
        NAMED_BAR(barid, 256);

        // ---- phase 2: mma bf16x3, acc stays in registers ----
        float acc[2][4][4];
#pragma unroll
        for (int mi = 0; mi < 2; mi++)
#pragma unroll
            for (int ni = 0; ni < 4; ni++)
#pragma unroll
                for (int r = 0; r < 4; r++) acc[mi][ni][r] = 0.f;

#pragma unroll
        for (int kk = 0; kk < 8; kk++) {
            uint32_t ah[2][4], al[2][4];
#pragma unroll
            for (int mi = 0; mi < 2; mi++) {
                const int row = wm * 32 + mi * 16 + lrow;
                const uint32_t boff =
                    (uint32_t)(row * (A_LDA * 2) + (kk * 16 + lcol) * 2);
                ldsm4(ah[mi], nh_smb + boff);
                ldsm4(al[mi], nl_smb + boff);
            }
#pragma unroll
            for (int grp = 0; grp < 2; grp++) {
                uint32_t bh[4], bl[4];
                const uint32_t boff =
                    (uint32_t)((kk * 16 + lrow) * (A_LDA * 2) +
                               (wn * 32 + grp * 16 + lcol) * 2);
                ldsm4t(bh, ah_smb + boff);
                ldsm4t(bl, al_smb + boff);
#pragma unroll
                for (int mi = 0; mi < 2; mi++)
#pragma unroll
                    for (int jj = 0; jj < 2; jj++) {
                        float* d = acc[mi][grp * 2 + jj];
                        mma16816(d, ah[mi], bh + 2 * jj);
                        mma16816(d, ah[mi], bl + 2 * jj);
                        mma16816(d, al[mi], bh + 2 * jj);
                    }
            }
        }

        // ---- phase 3: fragment-resident softmax + pooled ----
        {
            float es[8], pl[8];
#pragma unroll
            for (int c = 0; c < 8; c++) { es[c] = 0.f; pl[c] = 0.f; }

#pragma unroll
            for (int mi = 0; mi < 2; mi++)
#pragma unroll
                for (int hr = 0; hr < 2; hr++) {
                    const int trow = wm * 32 + mi * 16 + qrow + 8 * hr;
#pragma unroll
                    for (int ni = 0; ni < 4; ni++) {
                        const int col = wn * 32 + ni * 8 + qc;
                        float2 hp = upk_bf2(
                            *(const uint32_t*)(n_h + trow * A_LDA + col));
                        float2 lp = upk_bf2(
                            *(const uint32_t*)(n_l + trow * A_LDA + col));
                        float n0 = hp.x + lp.x, n1 = hp.y + lp.y;
                        float v0 = acc[mi][ni][hr * 2 + 0];
                        float v1 = acc[mi][ni][hr * 2 + 1];
                        v0 = (v0 > 0.f) ? v0 : ALPHA * v0;
                        v1 = (v1 > 0.f) ? v1 : ALPHA * v1;
                        float e0 = __expf(v0), e1 = __expf(v1);
                        es[ni * 2 + 0] += e0;
                        es[ni * 2 + 1] += e1;
                        pl[ni * 2 + 0] += e0 * n0;
                        pl[ni * 2 + 1] += e1 * n1;
                    }
                }
#pragma unroll
            for (int c = 0; c < 8; c++) {
#pragma unroll
                for (int m = 4; m <= 16; m <<= 1) {
                    es[c] += __shfl_xor_sync(0xffffffffu, es[c], m);
                    pl[c] += __shfl_xor_sync(0xffffffffu, pl[c], m);
                }
            }
            if (lane < 4) {
                float* dst = g_pooled + (size_t)(tile * 2 + wm) * 128 +
                             wn * 32 + 2 * lane;
#pragma unroll
                for (int ni = 0; ni < 4; ni++) {
                    float2 v = make_float2(__fdividef(pl[2 * ni], es[2 * ni]),
                                           __fdividef(pl[2 * ni + 1], es[2 * ni + 1]));
                    *(float2*)(dst + ni * 8) = v;
                }
            }
        }
        NAMED_BAR(barid, 256);   // protect n_h/n_l before next split
    }
}

// ============================================================================
// disf (unchanged from R7): permuted dgf, 128-row tiles, wmma bf16x3.
// ============================================================================
#define D_LDW 136
#define D_LDG 88
#define DS_W2H 0
#define DS_W2L 21760
#define DS_HB  43520
#define DS_HSZ 45056
#define SMEM_DISF 133632

__global__ void __launch_bounds__(512, 1)
disf_wmma_kernel(const float* __restrict__ g, const float* __restrict__ f,
                 const float* __restrict__ gn, const float* __restrict__ fn,
                 const float* __restrict__ w2, const float* __restrict__ b2,
                 float* __restrict__ disf) {
    extern __shared__ char sm[];
    __nv_bfloat16* w2h = (__nv_bfloat16*)(sm + DS_W2H);  // [80][136]
    __nv_bfloat16* w2l = (__nv_bfloat16*)(sm + DS_W2L);

    const int tid = threadIdx.x;
    const int half = tid >> 8;
    const int u = tid & 255;
    const int bid = blockIdx.x;

    for (int idx = tid; idx < 80 * 128; idx += 512) {
        int ch = idx >> 7, dd = idx & 127;
        float v = 0.f;
        if (ch < 64) v = w2[(3 + ch) * 128 + dd];
        else if (ch < 67) v = w2[(ch - 64) * 128 + dd];
        else if (ch < 69) v = w2[ch * 128 + dd];
        else if (ch == 69) v = b2[dd];
        __nv_bfloat16 h, l;
        bf16_split(v, h, l);
        w2h[ch * D_LDW + dd] = h;
        w2l[ch * D_LDW + dd] = l;
    }
    __syncthreads();

    char* hb = sm + DS_HB + half * DS_HSZ;
    __nv_bfloat16* dgh = (__nv_bfloat16*)hb;             // [128][88]
    __nv_bfloat16* dgl = (__nv_bfloat16*)(hb + 22528);
    const int barid = 1 + half;

    const int w = u >> 5;
    const int wm = w & 3;
    const int wn = w >> 2;
    const int r = u >> 1;
    const int q = u & 1;
    const int p = r >> 5;

    const int nt = (NTILES2 - bid + GRID - 1) / GRID;
    for (int j = half; j < nt; j += 2) {
        const int tile = bid + j * GRID;
        const int grow = tile * 128 + r;

        {
            const float4* fnp = (const float4*)(fn + (size_t)grow * 64 + q * 32);
            const float4* fp =
                (const float4*)(f + (size_t)(tile * 4 + p) * 64 + q * 32);
            float pf[32];
            float df2 = 0.f;
#pragma unroll
            for (int i = 0; i < 8; i++) {
                float4 A = fnp[i], F = fp[i];
                pf[i * 4 + 0] = F.x - A.x;
                pf[i * 4 + 1] = F.y - A.y;
                pf[i * 4 + 2] = F.z - A.z;
                pf[i * 4 + 3] = F.w - A.w;
                float t0 = F.x - 2.f * A.x, t1 = F.y - 2.f * A.y;
                float t2 = F.z - 2.f * A.z, t3 = F.w - 2.f * A.w;
                df2 += t0 * t0 + t1 * t1 + t2 * t2 + t3 * t3;
            }
            uint4* dsth = (uint4*)(dgh + r * D_LDG + q * 32);
            uint4* dstl = (uint4*)(dgl + r * D_LDG + q * 32);
#pragma unroll
            for (int b = 0; b < 4; b++) {
                uint32_t hh[4], ll[4];
#pragma unroll
                for (int i = 0; i < 4; i++) {
                    __nv_bfloat16 h0, l0, h1, l1;
                    bf16_split(pf[b * 8 + 2 * i], h0, l0);
                    bf16_split(pf[b * 8 + 2 * i + 1], h1, l1);
                    hh[i] = pack2(h0, h1);
                    ll[i] = pack2(l0, l1);
                }
                dsth[b] = make_uint4(hh[0], hh[1], hh[2], hh[3]);
                dstl[b] = make_uint4(ll[0], ll[1], ll[2], ll[3]);
            }

            df2 += __shfl_xor_sync(0xffffffffu, df2, 1);

            if (q == 0) {
                float tail[16];
#pragma unroll
                for (int i = 0; i < 16; i++) tail[i] = 0.f;
                float dg2 = 0.f;
#pragma unroll
                for (int c = 0; c < 3; c++) {
                    float gv = g[(size_t)(tile * 4 + p) * 3 + c];
                    float gnv = gn[(size_t)grow * 3 + c];
                    tail[c] = gv - gnv;
                    float t = gv - 2.f * gnv;
                    dg2 += t * t;
                }
                tail[3] = sqrtf(dg2);
                tail[4] = sqrtf(df2);
                tail[5] = 1.0f;
                uint32_t th[8], tl[8];
#pragma unroll
                for (int i = 0; i < 8; i++) {
                    __nv_bfloat16 h0, l0, h1, l1;
                    bf16_split(tail[2 * i], h0, l0);
                    bf16_split(tail[2 * i + 1], h1, l1);
                    th[i] = pack2(h0, h1);
                    tl[i] = pack2(l0, l1);
                }
                uint4* dh = (uint4*)(dgh + r * D_LDG + 64);
                uint4* dl = (uint4*)(dgl + r * D_LDG + 64);
                dh[0] = make_uint4(th[0], th[1], th[2], th[3]);
                dh[1] = make_uint4(th[4], th[5], th[6], th[7]);
                dl[0] = make_uint4(tl[0], tl[1], tl[2], tl[3]);
                dl[1] = make_uint4(tl[4], tl[5], tl[6], tl[7]);
            }
        }
        NAMED_BAR(barid, 256);

        {
            wmma::fragment<wmma::accumulator, 16, 16, 16, float> acc[2][4];
#pragma unroll
            for (int mi = 0; mi < 2; mi++)
#pragma unroll
                for (int ni = 0; ni < 4; ni++)
                    wmma::fill_fragment(acc[mi][ni], 0.0f);
#pragma unroll
            for (int kk = 0; kk < 5; kk++) {
                wmma::fragment<wmma::matrix_a, 16, 16, 16, __nv_bfloat16,
                               wmma::row_major> dh[2], dl[2];
#pragma unroll
                for (int mi = 0; mi < 2; mi++) {
                    const int row = wm * 32 + mi * 16;
                    wmma::load_matrix_sync(dh[mi], dgh + row * D_LDG + kk * 16, D_LDG);
                    wmma::load_matrix_sync(dl[mi], dgl + row * D_LDG + kk * 16, D_LDG);
                }
#pragma unroll
                for (int ni = 0; ni < 4; ni++) {
                    wmma::fragment<wmma::matrix_b, 16, 16, 16, __nv_bfloat16,
                                   wmma::row_major> wh, wl;
                    const int col = wn * 64 + ni * 16;
                    wmma::load_matrix_sync(wh, w2h + kk * 16 * D_LDW + col, D_LDW);
                    wmma::load_matrix_sync(wl, w2l + kk * 16 * D_LDW + col, D_LDW);
#pragma unroll
                    for (int mi = 0; mi < 2; mi++) {
                        wmma::mma_sync(acc[mi][ni], dh[mi], wh, acc[mi][ni]);
                        wmma::mma_sync(acc[mi][ni], dh[mi], wl, acc[mi][ni]);
                        wmma::mma_sync(acc[mi][ni], dl[mi], wh, acc[mi][ni]);
                    }
                }
            }
            float* dst = disf + (size_t)tile * 128 * 128;
#pragma unroll
            for (int mi = 0; mi < 2; mi++)
#pragma unroll
                for (int ni = 0; ni < 4; ni++)
                    wmma::store_matrix_sync(
                        dst + (wm * 32 + mi * 16) * 128 + wn * 64 + ni * 16,
                        acc[mi][ni], 128, wmma::mem_row_major);
        }
        NAMED_BAR(barid, 256);
    }
}

// ============================================================================
// out = pooled @ w1 + b1 via wmma bf16x3 (unchanged from R7).
// ============================================================================
#define O_LDW 136
#define O_LDE 132
#define OT_WH 0
#define OT_WL 34816
#define OT_B1 69632
#define OT_PH 70144
#define OT_PL 87552
#define OT_ES 104960
#define SMEM_OUT 138752

__global__ void __launch_bounds__(256, 1)
out_wmma_kernel(const float* __restrict__ w1, const float* __restrict__ b1,
                float* __restrict__ out) {
    extern __shared__ char sm[];
    __nv_bfloat16* w1h = (__nv_bfloat16*)(sm + OT_WH);
    __nv_bfloat16* w1l = (__nv_bfloat16*)(sm + OT_WL);
    float* b1s = (float*)(sm + OT_B1);
    __nv_bfloat16* p_h = (__nv_bfloat16*)(sm + OT_PH);
    __nv_bfloat16* p_l = (__nv_bfloat16*)(sm + OT_PL);
    float* e_s = (float*)(sm + OT_ES);

    const int tid = threadIdx.x;
    const int w = tid >> 5;
    const int wm = w & 1;
    const int wn = w >> 1;

    for (int idx = tid; idx < 128 * 128; idx += 256) {
        int j = idx >> 7, d = idx & 127;
        __nv_bfloat16 h, l;
        bf16_split(w1[idx], h, l);
        w1h[j * O_LDW + d] = h;
        w1l[j * O_LDW + d] = l;
    }
    if (tid < 128) b1s[tid] = b1[tid];
    __syncthreads();

    for (int tile = blockIdx.x; tile < NPTS / 64; tile += GRID) {
        const float4* gsrc = (const float4*)(g_pooled + (size_t)tile * 8192);
#pragma unroll
        for (int q = 0; q < 8; q++) {
            int v = tid + 256 * q;
            float4 x = gsrc[v];
            __nv_bfloat16 h0, l0, h1, l1, h2, l2, h3, l3;
            bf16_split(x.x, h0, l0);
            bf16_split(x.y, h1, l1);
            bf16_split(x.z, h2, l2);
            bf16_split(x.w, h3, l3);
            int fidx = v * 4;
            int r = fidx >> 7, c = fidx & 127;
            *(uint2*)(p_h + r * O_LDW + c) = make_uint2(pack2(h0, h1), pack2(h2, h3));
            *(uint2*)(p_l + r * O_LDW + c) = make_uint2(pack2(l0, l1), pack2(l2, l3));
        }
        __syncthreads();

        {
            wmma::fragment<wmma::accumulator, 16, 16, 16, float> acc[2][2];
#pragma unroll
            for (int mi = 0; mi < 2; mi++)
#pragma unroll
                for (int ni = 0; ni < 2; ni++)
                    wmma::fill_fragment(acc[mi][ni], 0.0f);
#pragma unroll
            for (int kk = 0; kk < 8; kk++) {
                wmma::fragment<wmma::matrix_a, 16, 16, 16, __nv_bfloat16,
                               wmma::row_major> ph[2], pl[2];
                wmma::fragment<wmma::matrix_b, 16, 16, 16, __nv_bfloat16,
                               wmma::row_major> wh[2], wl[2];
#pragma unroll
                for (int mi = 0; mi < 2; mi++) {
                    const int row = wm * 32 + mi * 16;
                    wmma::load_matrix_sync(ph[mi], p_h + row * O_LDW + kk * 16, O_LDW);
                    wmma::load_matrix_sync(pl[mi], p_l + row * O_LDW + kk * 16, O_LDW);
                }
#pragma unroll
                for (int ni = 0; ni < 2; ni++) {
                    const int col = wn * 32 + ni * 16;
                    wmma::load_matrix_sync(wh[ni], w1h + kk * 16 * O_LDW + col, O_LDW);
                    wmma::load_matrix_sync(wl[ni], w1l + kk * 16 * O_LDW + col, O_LDW);
                }
#pragma unroll
                for (int mi = 0; mi < 2; mi++)
#pragma unroll
                    for (int ni = 0; ni < 2; ni++) {
                        wmma::mma_sync(acc[mi][ni], ph[mi], wh[ni], acc[mi][ni]);
                        wmma::mma_sync(acc[mi][ni], ph[mi], wl[ni], acc[mi][ni]);
                        wmma::mma_sync(acc[mi][ni], pl[mi], wh[ni], acc[mi][ni]);
                    }
            }
#pragma unroll
            for (int mi = 0; mi < 2; mi++)
#pragma unroll
                for (int ni = 0; ni < 2; ni++)
                    wmma::store_matrix_sync(
                        e_s + (wm * 32 + mi * 16) * O_LDE + wn * 32 + ni * 16,
                        acc[mi][ni], O_LDE, wmma::mem_row_major);
        }
        __syncthreads();

        {
            float* dst = out + (size_t)tile * 8192;
#pragma unroll
            for (int i = 0; i < 8; i++) {
                int v = tid + 256 * i;
                int rr = v >> 5, c4 = v & 31;
                float4 e4 = *(const float4*)(e_s + rr * O_LDE + c4 * 4);
                float4 b4 = *(const float4*)(b1s + c4 * 4);
                e4.x += b4.x; e4.y += b4.y; e4.z += b4.z; e4.w += b4.w;
                ((float4*)dst)[v] = e4;
            }
        }
        __syncthreads();
    }
}

// ============================================================================
// launch
// ============================================================================
extern "C" void kernel_launch(void* const* d_in, const int* in_sizes, int n_in,
                              void* d_out, int out_size) {
    const float* g = (const float*)d_in[0];
    const float* f = (const float*)d_in[1];
    const float* gn = (const float*)d_in[2];
    const float* fn = (const float*)d_in[3];
    const float* nfn = (const float*)d_in[4];
    const float* a = (const float*)d_in[5];
    const float* w2 = (const float*)d_in[6];
    const float* b2 = (const float*)d_in[7];
    const float* w1 = (const float*)d_in[8];
    const float* b1 = (const float*)d_in[9];

    float* out = (float*)d_out;
    float* disf = out + (size_t)NPTS * DP;

    cudaFuncSetAttribute(attn_mma_kernel,
                         cudaFuncAttributeMaxDynamicSharedMemorySize, SMEM_ATTN);
    cudaFuncSetAttribute(disf_wmma_kernel,
                         cudaFuncAttributeMaxDynamicSharedMemorySize, SMEM_DISF);
    cudaFuncSetAttribute(out_wmma_kernel,
                         cudaFuncAttributeMaxDynamicSharedMemorySize, SMEM_OUT);

    attn_mma_kernel<<<GRID, 512, SMEM_ATTN>>>(nfn, a);
    disf_wmma_kernel<<<GRID, 512, SMEM_DISF>>>(g, f, gn, fn, w2, b2, disf);
    out_wmma_kernel<<<GRID, 256, SMEM_OUT>>>(w1, b1, out);
}

// round 10
// speedup vs baseline: 3.3383x; 1.0951x over previous
#include <cuda_runtime.h>
#include <cuda_bf16.h>
#include <mma.h>
#include <math.h>
#include <stdint.h>

using namespace nvcuda;

// ---------------------------------------------------------------------------
#define BB 4
#define NN 4096
#define KK 32
#define DP 128
#define DC 69
#define NPTS (BB*NN)
#define ALPHA 0.2f

#define GRID 152
#define NTILES 8192           // attn: 64 ptk-rows per tile
#define NTILES2 4096          // disf: 128 ptk-rows per tile

__device__ float g_pooled[NPTS * DP];

__device__ __forceinline__ void bf16_split(float v, __nv_bfloat16& h,
                                           __nv_bfloat16& l) {
    h = __float2bfloat16_rn(v);
    l = __float2bfloat16_rn(v - __bfloat162float(h));
}
__device__ __forceinline__ uint32_t pack2(__nv_bfloat16 a, __nv_bfloat16 b) {
    return (uint32_t)__bfloat16_as_ushort(a) |
           ((uint32_t)__bfloat16_as_ushort(b) << 16);
}
__device__ __forceinline__ float2 upk_bf2(uint32_t v) {
    __nv_bfloat162 b = *(__nv_bfloat162*)&v;
    return make_float2(__bfloat162float(b.x), __bfloat162float(b.y));
}
__device__ __forceinline__ uint32_t smem_u32(const void* p) {
    uint32_t a;
    asm("{ .reg .u64 t; cvta.to.shared.u64 t, %1; cvt.u32.u64 %0, t; }"
        : "=r"(a) : "l"(p));
    return a;
}
#define NAMED_BAR(id, cnt) \
    asm volatile("bar.sync %0, %1;" :: "r"(id), "r"(cnt) : "memory")

__device__ __forceinline__ void ldsm4(uint32_t* r, uint32_t addr) {
    asm volatile("ldmatrix.sync.aligned.m8n8.x4.shared.b16 {%0,%1,%2,%3}, [%4];"
        : "=r"(r[0]), "=r"(r[1]), "=r"(r[2]), "=r"(r[3]) : "r"(addr));
}
__device__ __forceinline__ void ldsm4t(uint32_t* r, uint32_t addr) {
    asm volatile("ldmatrix.sync.aligned.m8n8.x4.trans.shared.b16 {%0,%1,%2,%3}, [%4];"
        : "=r"(r[0]), "=r"(r[1]), "=r"(r[2]), "=r"(r[3]) : "r"(addr));
}
__device__ __forceinline__ void mma16816(float* d, const uint32_t* a,
                                         const uint32_t* b) {
    asm volatile("mma.sync.aligned.m16n8k16.row.col.f32.bf16.bf16.f32 "
        "{%0,%1,%2,%3}, {%4,%5,%6,%7}, {%8,%9}, {%0,%1,%2,%3};"
        : "+f"(d[0]), "+f"(d[1]), "+f"(d[2]), "+f"(d[3])
        : "r"(a[0]), "r"(a[1]), "r"(a[2]), "r"(a[3]), "r"(b[0]), "r"(b[1]));
}

// ---------------------------------------------------------------------------
// Fused kernel smem layout (bytes)
// ---------------------------------------------------------------------------
#define A_LDA 136
#define D_LDW 136
#define D_LDG 88
#define FX_AH   0          // [128][136] bf16 = 34816
#define FX_AL   34816
#define FX_NH   69632      // [64][136] bf16 = 17408
#define FX_NL   87040
#define FX_W2H  104448     // [80][136] bf16 = 21760
#define FX_W2L  126208
#define FX_DGH  147968     // [128][88] bf16 = 22528
#define FX_DGL  170496
#define SMEM_FUSED 193024

// ============================================================================
// Fused attn+disf: warps 0-7 = attn pipeline, warps 8-15 = disf pipeline.
// ============================================================================
__global__ void __launch_bounds__(512, 1)
fused_kernel(const float* __restrict__ nfn, const float* __restrict__ a,
             const float* __restrict__ g, const float* __restrict__ f,
             const float* __restrict__ gn, const float* __restrict__ fn,
             const float* __restrict__ w2, const float* __restrict__ b2,
             float* __restrict__ disf) {
    extern __shared__ char sm[];
    __nv_bfloat16* a_h = (__nv_bfloat16*)(sm + FX_AH);
    __nv_bfloat16* a_l = (__nv_bfloat16*)(sm + FX_AL);
    __nv_bfloat16* n_h = (__nv_bfloat16*)(sm + FX_NH);
    __nv_bfloat16* n_l = (__nv_bfloat16*)(sm + FX_NL);
    __nv_bfloat16* w2h = (__nv_bfloat16*)(sm + FX_W2H);
    __nv_bfloat16* w2l = (__nv_bfloat16*)(sm + FX_W2L);
    __nv_bfloat16* dgh = (__nv_bfloat16*)(sm + FX_DGH);
    __nv_bfloat16* dgl = (__nv_bfloat16*)(sm + FX_DGL);

    const int tid = threadIdx.x;
    const int bid = blockIdx.x;

    // one-time: split a (attn) and permuted w2+bias (disf)
    for (int idx = tid; idx < 128 * 128; idx += 512) {
        int j = idx >> 7, d = idx & 127;
        __nv_bfloat16 h, l;
        bf16_split(a[idx], h, l);
        a_h[j * A_LDA + d] = h;
        a_l[j * A_LDA + d] = l;
    }
    for (int idx = tid; idx < 80 * 128; idx += 512) {
        int ch = idx >> 7, dd = idx & 127;
        float v = 0.f;
        if (ch < 64) v = w2[(3 + ch) * 128 + dd];
        else if (ch < 67) v = w2[(ch - 64) * 128 + dd];
        else if (ch < 69) v = w2[ch * 128 + dd];
        else if (ch == 69) v = b2[dd];
        __nv_bfloat16 h, l;
        bf16_split(v, h, l);
        w2h[ch * D_LDW + dd] = h;
        w2l[ch * D_LDW + dd] = l;
    }
    __syncthreads();

    if (tid < 256) {
        // ==================== attn pipeline (warps 0-7) ====================
        const int u = tid;
        const int w = u >> 5;
        const int lane = u & 31;
        const int wm = w & 1;
        const int wn = w >> 1;
        const int qrow = lane >> 2;
        const int qc = (lane & 3) << 1;
        const int lrow = lane & 15;
        const int lcol = (lane >> 4) << 3;
        const uint32_t nh_smb = smem_u32(n_h);
        const uint32_t nl_smb = smem_u32(n_l);
        const uint32_t ah_smb = smem_u32(a_h);
        const uint32_t al_smb = smem_u32(a_l);

        const int nt = (NTILES - bid + GRID - 1) / GRID;
        for (int j = 0; j < nt; j++) {
            const int tile = bid + j * GRID;

            // ---- phase 1: LDG + split -> n_h/n_l ----
            const float4* gsrc = (const float4*)(nfn + (size_t)tile * 8192);
#pragma unroll
            for (int q = 0; q < 8; q++) {
                int v = u + 256 * q;
                float4 x = gsrc[v];
                __nv_bfloat16 h0, l0, h1, l1, h2, l2, h3, l3;
                bf16_split(x.x, h0, l0);
                bf16_split(x.y, h1, l1);
                bf16_split(x.z, h2, l2);
                bf16_split(x.w, h3, l3);
                int fidx = v * 4;
                int r = fidx >> 7, c = fidx & 127;
                *(uint2*)(n_h + r * A_LDA + c) =
                    make_uint2(pack2(h0, h1), pack2(h2, h3));
                *(uint2*)(n_l + r * A_LDA + c) =
                    make_uint2(pack2(l0, l1), pack2(l2, l3));
            }
            NAMED_BAR(1, 256);

            // ---- phase 2: mma bf16x3, save h A-frags for epilogue ----
            float acc[2][4][4];
#pragma unroll
            for (int mi = 0; mi < 2; mi++)
#pragma unroll
                for (int ni = 0; ni < 4; ni++)
#pragma unroll
                    for (int r = 0; r < 4; r++) acc[mi][ni][r] = 0.f;

            uint32_t nsav[2][2][4];   // [mi][kk-local][reg] nfn_h fragments

#pragma unroll
            for (int kk = 0; kk < 8; kk++) {
                uint32_t ah[2][4], al[2][4];
#pragma unroll
                for (int mi = 0; mi < 2; mi++) {
                    const int row = wm * 32 + mi * 16 + lrow;
                    const uint32_t boff =
                        (uint32_t)(row * (A_LDA * 2) + (kk * 16 + lcol) * 2);
                    ldsm4(ah[mi], nh_smb + boff);
                    ldsm4(al[mi], nl_smb + boff);
                }
                if ((kk >> 1) == wn) {
#pragma unroll
                    for (int mi = 0; mi < 2; mi++)
#pragma unroll
                        for (int r = 0; r < 4; r++)
                            nsav[mi][kk & 1][r] = ah[mi][r];
                }
#pragma unroll
                for (int grp = 0; grp < 2; grp++) {
                    uint32_t bh[4], bl[4];
                    const uint32_t boff =
                        (uint32_t)((kk * 16 + lrow) * (A_LDA * 2) +
                                   (wn * 32 + grp * 16 + lcol) * 2);
                    ldsm4t(bh, ah_smb + boff);
                    ldsm4t(bl, al_smb + boff);
#pragma unroll
                    for (int mi = 0; mi < 2; mi++)
#pragma unroll
                        for (int jj = 0; jj < 2; jj++) {
                            float* d = acc[mi][grp * 2 + jj];
                            mma16816(d, ah[mi], bh + 2 * jj);
                            mma16816(d, ah[mi], bl + 2 * jj);
                            mma16816(d, al[mi], bh + 2 * jj);
                        }
                }
            }

            // ---- phase 3: fragment-resident softmax + pooled ----
            {
                float es[8], pl[8];
#pragma unroll
                for (int c = 0; c < 8; c++) { es[c] = 0.f; pl[c] = 0.f; }

#pragma unroll
                for (int mi = 0; mi < 2; mi++)
#pragma unroll
                    for (int hr = 0; hr < 2; hr++) {
                        const int trow = wm * 32 + mi * 16 + qrow + 8 * hr;
#pragma unroll
                        for (int ni = 0; ni < 4; ni++) {
                            const int col = wn * 32 + ni * 8 + qc;
                            float2 hp = upk_bf2(
                                nsav[mi][ni >> 1][hr + 2 * (ni & 1)]);
                            float2 lp = upk_bf2(
                                *(const uint32_t*)(n_l + trow * A_LDA + col));
                            float n0 = hp.x + lp.x, n1 = hp.y + lp.y;
                            float v0 = acc[mi][ni][hr * 2 + 0];
                            float v1 = acc[mi][ni][hr * 2 + 1];
                            v0 = (v0 > 0.f) ? v0 : ALPHA * v0;
                            v1 = (v1 > 0.f) ? v1 : ALPHA * v1;
                            float e0 = __expf(v0), e1 = __expf(v1);
                            es[ni * 2 + 0] += e0;
                            es[ni * 2 + 1] += e1;
                            pl[ni * 2 + 0] += e0 * n0;
                            pl[ni * 2 + 1] += e1 * n1;
                        }
                    }
#pragma unroll
                for (int c = 0; c < 8; c++) {
#pragma unroll
                    for (int m = 4; m <= 16; m <<= 1) {
                        es[c] += __shfl_xor_sync(0xffffffffu, es[c], m);
                        pl[c] += __shfl_xor_sync(0xffffffffu, pl[c], m);
                    }
                }
                if (lane < 4) {
                    float* dst = g_pooled + (size_t)(tile * 2 + wm) * 128 +
                                 wn * 32 + 2 * lane;
#pragma unroll
                    for (int ni = 0; ni < 4; ni++) {
                        float2 v =
                            make_float2(__fdividef(pl[2 * ni], es[2 * ni]),
                                        __fdividef(pl[2 * ni + 1], es[2 * ni + 1]));
                        *(float2*)(dst + ni * 8) = v;
                    }
                }
            }
            NAMED_BAR(1, 256);   // protect n_h/n_l before next split
        }
    } else {
        // ==================== disf pipeline (warps 8-15) ====================
        const int u = tid - 256;
        const int w = u >> 5;
        const int wm = w & 3;
        const int wn = w >> 2;
        const int r = u >> 1;
        const int q = u & 1;
        const int p = r >> 5;

        const int nt = (NTILES2 - bid + GRID - 1) / GRID;
        for (int j = 0; j < nt; j++) {
            const int tile = bid + j * GRID;
            const int grow = tile * 128 + r;

            // ---- build dgf straight from LDG ----
            {
                const float4* fnp =
                    (const float4*)(fn + (size_t)grow * 64 + q * 32);
                const float4* fp =
                    (const float4*)(f + (size_t)(tile * 4 + p) * 64 + q * 32);
                float pf[32];
                float df2 = 0.f;
#pragma unroll
                for (int i = 0; i < 8; i++) {
                    float4 A = fnp[i], F = fp[i];
                    pf[i * 4 + 0] = F.x - A.x;
                    pf[i * 4 + 1] = F.y - A.y;
                    pf[i * 4 + 2] = F.z - A.z;
                    pf[i * 4 + 3] = F.w - A.w;
                    float t0 = F.x - 2.f * A.x, t1 = F.y - 2.f * A.y;
                    float t2 = F.z - 2.f * A.z, t3 = F.w - 2.f * A.w;
                    df2 += t0 * t0 + t1 * t1 + t2 * t2 + t3 * t3;
                }
                uint4* dsth = (uint4*)(dgh + r * D_LDG + q * 32);
                uint4* dstl = (uint4*)(dgl + r * D_LDG + q * 32);
#pragma unroll
                for (int b = 0; b < 4; b++) {
                    uint32_t hh[4], ll[4];
#pragma unroll
                    for (int i = 0; i < 4; i++) {
                        __nv_bfloat16 h0, l0, h1, l1;
                        bf16_split(pf[b * 8 + 2 * i], h0, l0);
                        bf16_split(pf[b * 8 + 2 * i + 1], h1, l1);
                        hh[i] = pack2(h0, h1);
                        ll[i] = pack2(l0, l1);
                    }
                    dsth[b] = make_uint4(hh[0], hh[1], hh[2], hh[3]);
                    dstl[b] = make_uint4(ll[0], ll[1], ll[2], ll[3]);
                }

                df2 += __shfl_xor_sync(0xffffffffu, df2, 1);

                if (q == 0) {
                    float tail[16];
#pragma unroll
                    for (int i = 0; i < 16; i++) tail[i] = 0.f;
                    float dg2 = 0.f;
#pragma unroll
                    for (int c = 0; c < 3; c++) {
                        float gv = g[(size_t)(tile * 4 + p) * 3 + c];
                        float gnv = gn[(size_t)grow * 3 + c];
                        tail[c] = gv - gnv;
                        float t = gv - 2.f * gnv;
                        dg2 += t * t;
                    }
                    tail[3] = sqrtf(dg2);
                    tail[4] = sqrtf(df2);
                    tail[5] = 1.0f;
                    uint32_t th[8], tl[8];
#pragma unroll
                    for (int i = 0; i < 8; i++) {
                        __nv_bfloat16 h0, l0, h1, l1;
                        bf16_split(tail[2 * i], h0, l0);
                        bf16_split(tail[2 * i + 1], h1, l1);
                        th[i] = pack2(h0, h1);
                        tl[i] = pack2(l0, l1);
                    }
                    uint4* dh = (uint4*)(dgh + r * D_LDG + 64);
                    uint4* dl = (uint4*)(dgl + r * D_LDG + 64);
                    dh[0] = make_uint4(th[0], th[1], th[2], th[3]);
                    dh[1] = make_uint4(th[4], th[5], th[6], th[7]);
                    dl[0] = make_uint4(tl[0], tl[1], tl[2], tl[3]);
                    dl[1] = make_uint4(tl[4], tl[5], tl[6], tl[7]);
                }
            }
            NAMED_BAR(2, 256);

            // ---- wmma bf16x3 (K=80), store straight to gmem ----
            {
                wmma::fragment<wmma::accumulator, 16, 16, 16, float> acc[2][4];
#pragma unroll
                for (int mi = 0; mi < 2; mi++)
#pragma unroll
                    for (int ni = 0; ni < 4; ni++)
                        wmma::fill_fragment(acc[mi][ni], 0.0f);
#pragma unroll
                for (int kk = 0; kk < 5; kk++) {
                    wmma::fragment<wmma::matrix_a, 16, 16, 16, __nv_bfloat16,
                                   wmma::row_major> dh[2], dl[2];
#pragma unroll
                    for (int mi = 0; mi < 2; mi++) {
                        const int row = wm * 32 + mi * 16;
                        wmma::load_matrix_sync(dh[mi],
                            dgh + row * D_LDG + kk * 16, D_LDG);
                        wmma::load_matrix_sync(dl[mi],
                            dgl + row * D_LDG + kk * 16, D_LDG);
                    }
#pragma unroll
                    for (int ni = 0; ni < 4; ni++) {
                        wmma::fragment<wmma::matrix_b, 16, 16, 16, __nv_bfloat16,
                                       wmma::row_major> wh, wl;
                        const int col = wn * 64 + ni * 16;
                        wmma::load_matrix_sync(wh,
                            w2h + kk * 16 * D_LDW + col, D_LDW);
                        wmma::load_matrix_sync(wl,
                            w2l + kk * 16 * D_LDW + col, D_LDW);
#pragma unroll
                        for (int mi = 0; mi < 2; mi++) {
                            wmma::mma_sync(acc[mi][ni], dh[mi], wh, acc[mi][ni]);
                            wmma::mma_sync(acc[mi][ni], dh[mi], wl, acc[mi][ni]);
                            wmma::mma_sync(acc[mi][ni], dl[mi], wh, acc[mi][ni]);
                        }
                    }
                }
                float* dst = disf + (size_t)tile * 128 * 128;
#pragma unroll
                for (int mi = 0; mi < 2; mi++)
#pragma unroll
                    for (int ni = 0; ni < 4; ni++)
                        wmma::store_matrix_sync(
                            dst + (wm * 32 + mi * 16) * 128 + wn * 64 + ni * 16,
                            acc[mi][ni], 128, wmma::mem_row_major);
            }
            NAMED_BAR(2, 256);
        }
    }
}

// ============================================================================
// out = pooled @ w1 + b1 via wmma bf16x3 (unchanged).
// ============================================================================
#define O_LDW 136
#define O_LDE 132
#define OT_WH 0
#define OT_WL 34816
#define OT_B1 69632
#define OT_PH 70144
#define OT_PL 87552
#define OT_ES 104960
#define SMEM_OUT 138752

__global__ void __launch_bounds__(256, 1)
out_wmma_kernel(const float* __restrict__ w1, const float* __restrict__ b1,
                float* __restrict__ out) {
    extern __shared__ char sm[];
    __nv_bfloat16* w1h = (__nv_bfloat16*)(sm + OT_WH);
    __nv_bfloat16* w1l = (__nv_bfloat16*)(sm + OT_WL);
    float* b1s = (float*)(sm + OT_B1);
    __nv_bfloat16* p_h = (__nv_bfloat16*)(sm + OT_PH);
    __nv_bfloat16* p_l = (__nv_bfloat16*)(sm + OT_PL);
    float* e_s = (float*)(sm + OT_ES);

    const int tid = threadIdx.x;
    const int w = tid >> 5;
    const int wm = w & 1;
    const int wn = w >> 1;

    for (int idx = tid; idx < 128 * 128; idx += 256) {
        int j = idx >> 7, d = idx & 127;
        __nv_bfloat16 h, l;
        bf16_split(w1[idx], h, l);
        w1h[j * O_LDW + d] = h;
        w1l[j * O_LDW + d] = l;
    }
    if (tid < 128) b1s[tid] = b1[tid];
    __syncthreads();

    for (int tile = blockIdx.x; tile < NPTS / 64; tile += GRID) {
        const float4* gsrc = (const float4*)(g_pooled + (size_t)tile * 8192);
#pragma unroll
        for (int q = 0; q < 8; q++) {
            int v = tid + 256 * q;
            float4 x = gsrc[v];
            __nv_bfloat16 h0, l0, h1, l1, h2, l2, h3, l3;
            bf16_split(x.x, h0, l0);
            bf16_split(x.y, h1, l1);
            bf16_split(x.z, h2, l2);
            bf16_split(x.w, h3, l3);
            int fidx = v * 4;
            int r = fidx >> 7, c = fidx & 127;
            *(uint2*)(p_h + r * O_LDW + c) = make_uint2(pack2(h0, h1), pack2(h2, h3));
            *(uint2*)(p_l + r * O_LDW + c) = make_uint2(pack2(l0, l1), pack2(l2, l3));
        }
        __syncthreads();

        {
            wmma::fragment<wmma::accumulator, 16, 16, 16, float> acc[2][2];
#pragma unroll
            for (int mi = 0; mi < 2; mi++)
#pragma unroll
                for (int ni = 0; ni < 2; ni++)
                    wmma::fill_fragment(acc[mi][ni], 0.0f);
#pragma unroll
            for (int kk = 0; kk < 8; kk++) {
                wmma::fragment<wmma::matrix_a, 16, 16, 16, __nv_bfloat16,
                               wmma::row_major> ph[2], pl[2];
                wmma::fragment<wmma::matrix_b, 16, 16, 16, __nv_bfloat16,
                               wmma::row_major> wh[2], wl[2];
#pragma unroll
                for (int mi = 0; mi < 2; mi++) {
                    const int row = wm * 32 + mi * 16;
                    wmma::load_matrix_sync(ph[mi], p_h + row * O_LDW + kk * 16, O_LDW);
                    wmma::load_matrix_sync(pl[mi], p_l + row * O_LDW + kk * 16, O_LDW);
                }
#pragma unroll
                for (int ni = 0; ni < 2; ni++) {
                    const int col = wn * 32 + ni * 16;
                    wmma::load_matrix_sync(wh[ni], w1h + kk * 16 * O_LDW + col, O_LDW);
                    wmma::load_matrix_sync(wl[ni], w1l + kk * 16 * O_LDW + col, O_LDW);
                }
#pragma unroll
                for (int mi = 0; mi < 2; mi++)
#pragma unroll
                    for (int ni = 0; ni < 2; ni++) {
                        wmma::mma_sync(acc[mi][ni], ph[mi], wh[ni], acc[mi][ni]);
                        wmma::mma_sync(acc[mi][ni], ph[mi], wl[ni], acc[mi][ni]);
                        wmma::mma_sync(acc[mi][ni], pl[mi], wh[ni], acc[mi][ni]);
                    }
            }
#pragma unroll
            for (int mi = 0; mi < 2; mi++)
#pragma unroll
                for (int ni = 0; ni < 2; ni++)
                    wmma::store_matrix_sync(
                        e_s + (wm * 32 + mi * 16) * O_LDE + wn * 32 + ni * 16,
                        acc[mi][ni], O_LDE, wmma::mem_row_major);
        }
        __syncthreads();

        {
            float* dst = out + (size_t)tile * 8192;
#pragma unroll
            for (int i = 0; i < 8; i++) {
                int v = tid + 256 * i;
                int rr = v >> 5, c4 = v & 31;
                float4 e4 = *(const float4*)(e_s + rr * O_LDE + c4 * 4);
                float4 b4 = *(const float4*)(b1s + c4 * 4);
                e4.x += b4.x; e4.y += b4.y; e4.z += b4.z; e4.w += b4.w;
                ((float4*)dst)[v] = e4;
            }
        }
        __syncthreads();
    }
}

// ============================================================================
// launch
// ============================================================================
extern "C" void kernel_launch(void* const* d_in, const int* in_sizes, int n_in,
                              void* d_out, int out_size) {
    const float* g = (const float*)d_in[0];
    const float* f = (const float*)d_in[1];
    const float* gn = (const float*)d_in[2];
    const float* fn = (const float*)d_in[3];
    const float* nfn = (const float*)d_in[4];
    const float* a = (const float*)d_in[5];
    const float* w2 = (const float*)d_in[6];
    const float* b2 = (const float*)d_in[7];
    const float* w1 = (const float*)d_in[8];
    const float* b1 = (const float*)d_in[9];

    float* out = (float*)d_out;
    float* disf = out + (size_t)NPTS * DP;

    cudaFuncSetAttribute(fused_kernel,
                         cudaFuncAttributeMaxDynamicSharedMemorySize, SMEM_FUSED);
    cudaFuncSetAttribute(out_wmma_kernel,
                         cudaFuncAttributeMaxDynamicSharedMemorySize, SMEM_OUT);

    fused_kernel<<<GRID, 512, SMEM_FUSED>>>(nfn, a, g, f, gn, fn, w2, b2, disf);
    out_wmma_kernel<<<GRID, 256, SMEM_OUT>>>(w1, b1, out);
}

// round 11
// speedup vs baseline: 3.4494x; 1.0333x over previous
#include <cuda_runtime.h>
#include <cuda_bf16.h>
#include <mma.h>
#include <math.h>
#include <stdint.h>

using namespace nvcuda;

// ---------------------------------------------------------------------------
#define BB 4
#define NN 4096
#define KK 32
#define DP 128
#define DC 69
#define NPTS (BB*NN)
#define ALPHA 0.2f

#define GRID 152
#define NTILES 8192           // attn: 64 ptk-rows per tile
#define NTILES2 8192          // disf: 64 ptk-rows per tile

__device__ float g_pooled[NPTS * DP];

__device__ __forceinline__ void bf16_split(float v, __nv_bfloat16& h,
                                           __nv_bfloat16& l) {
    h = __float2bfloat16_rn(v);
    l = __float2bfloat16_rn(v - __bfloat162float(h));
}
__device__ __forceinline__ uint32_t pack2(__nv_bfloat16 a, __nv_bfloat16 b) {
    return (uint32_t)__bfloat16_as_ushort(a) |
           ((uint32_t)__bfloat16_as_ushort(b) << 16);
}
__device__ __forceinline__ float2 upk_bf2(uint32_t v) {
    __nv_bfloat162 b = *(__nv_bfloat162*)&v;
    return make_float2(__bfloat162float(b.x), __bfloat162float(b.y));
}
__device__ __forceinline__ uint32_t smem_u32(const void* p) {
    uint32_t a;
    asm("{ .reg .u64 t; cvta.to.shared.u64 t, %1; cvt.u32.u64 %0, t; }"
        : "=r"(a) : "l"(p));
    return a;
}
#define NAMED_BAR(id, cnt) \
    asm volatile("bar.sync %0, %1;" :: "r"(id), "r"(cnt) : "memory")

#define CP_ASYNC16(dst, src) \
    asm volatile("cp.async.cg.shared.global [%0], [%1], 16;" \
        :: "r"((uint32_t)(dst)), "l"(src) : "memory")
#define CP_COMMIT() asm volatile("cp.async.commit_group;" ::: "memory")
#define CP_WAIT0()  asm volatile("cp.async.wait_group 0;" ::: "memory")

__device__ __forceinline__ void ldsm4(uint32_t* r, uint32_t addr) {
    asm volatile("ldmatrix.sync.aligned.m8n8.x4.shared.b16 {%0,%1,%2,%3}, [%4];"
        : "=r"(r[0]), "=r"(r[1]), "=r"(r[2]), "=r"(r[3]) : "r"(addr));
}
__device__ __forceinline__ void ldsm4t(uint32_t* r, uint32_t addr) {
    asm volatile("ldmatrix.sync.aligned.m8n8.x4.trans.shared.b16 {%0,%1,%2,%3}, [%4];"
        : "=r"(r[0]), "=r"(r[1]), "=r"(r[2]), "=r"(r[3]) : "r"(addr));
}
__device__ __forceinline__ void mma16816(float* d, const uint32_t* a,
                                         const uint32_t* b) {
    asm volatile("mma.sync.aligned.m16n8k16.row.col.f32.bf16.bf16.f32 "
        "{%0,%1,%2,%3}, {%4,%5,%6,%7}, {%8,%9}, {%0,%1,%2,%3};"
        : "+f"(d[0]), "+f"(d[1]), "+f"(d[2]), "+f"(d[3])
        : "r"(a[0]), "r"(a[1]), "r"(a[2]), "r"(a[3]), "r"(b[0]), "r"(b[1]));
}

// ---------------------------------------------------------------------------
// Fused kernel smem layout (bytes)
// ---------------------------------------------------------------------------
#define A_LDA 136
#define D_LDW 136
#define D_LDG 88
#define FX_AH   0          // [128][136] bf16 = 34816
#define FX_AL   34816
#define FX_NH   69632      // [64][136] bf16 = 17408
#define FX_NL   87040
#define FX_RAW  104448     // [64][128] fp32 = 32768
#define FX_W2H  137216     // [80][136] bf16 = 21760
#define FX_W2L  158976
#define FX_DGH  180736     // [64][88] bf16 = 11264
#define FX_DGL  192000
#define SMEM_FUSED 203264

// ============================================================================
// Fused attn+disf: warps 0-7 = attn (cp.async pipelined), 8-15 = disf.
// ============================================================================
__global__ void __launch_bounds__(512, 1)
fused_kernel(const float* __restrict__ nfn, const float* __restrict__ a,
             const float* __restrict__ g, const float* __restrict__ f,
             const float* __restrict__ gn, const float* __restrict__ fn,
             const float* __restrict__ w2, const float* __restrict__ b2,
             float* __restrict__ disf) {
    extern __shared__ char sm[];
    __nv_bfloat16* a_h = (__nv_bfloat16*)(sm + FX_AH);
    __nv_bfloat16* a_l = (__nv_bfloat16*)(sm + FX_AL);
    __nv_bfloat16* n_h = (__nv_bfloat16*)(sm + FX_NH);
    __nv_bfloat16* n_l = (__nv_bfloat16*)(sm + FX_NL);
    float* raw = (float*)(sm + FX_RAW);
    __nv_bfloat16* w2h = (__nv_bfloat16*)(sm + FX_W2H);
    __nv_bfloat16* w2l = (__nv_bfloat16*)(sm + FX_W2L);
    __nv_bfloat16* dgh = (__nv_bfloat16*)(sm + FX_DGH);
    __nv_bfloat16* dgl = (__nv_bfloat16*)(sm + FX_DGL);

    const int tid = threadIdx.x;
    const int bid = blockIdx.x;

    // one-time: split a (attn) and permuted w2+bias (disf)
    for (int idx = tid; idx < 128 * 128; idx += 512) {
        int j = idx >> 7, d = idx & 127;
        __nv_bfloat16 h, l;
        bf16_split(a[idx], h, l);
        a_h[j * A_LDA + d] = h;
        a_l[j * A_LDA + d] = l;
    }
    for (int idx = tid; idx < 80 * 128; idx += 512) {
        int ch = idx >> 7, dd = idx & 127;
        float v = 0.f;
        if (ch < 64) v = w2[(3 + ch) * 128 + dd];
        else if (ch < 67) v = w2[(ch - 64) * 128 + dd];
        else if (ch < 69) v = w2[ch * 128 + dd];
        else if (ch == 69) v = b2[dd];
        __nv_bfloat16 h, l;
        bf16_split(v, h, l);
        w2h[ch * D_LDW + dd] = h;
        w2l[ch * D_LDW + dd] = l;
    }
    __syncthreads();

    if (tid < 256) {
        // ==================== attn pipeline (warps 0-7) ====================
        const int u = tid;
        const int w = u >> 5;
        const int lane = u & 31;
        const int wm = w & 1;
        const int wn = w >> 1;
        const int qrow = lane >> 2;
        const int qc = (lane & 3) << 1;
        const int lrow = lane & 15;
        const int lcol = (lane >> 4) << 3;
        const uint32_t nh_smb = smem_u32(n_h);
        const uint32_t nl_smb = smem_u32(n_l);
        const uint32_t ah_smb = smem_u32(a_h);
        const uint32_t al_smb = smem_u32(a_l);
        const uint32_t raw_smb = smem_u32(raw);

        const int nt = (NTILES - bid + GRID - 1) / GRID;

        // prologue: cp.async tile 0 -> raw
        {
            const char* src = (const char*)(nfn + (size_t)bid * 8192) + u * 16;
            uint32_t dst = raw_smb + u * 16;
#pragma unroll
            for (int q = 0; q < 8; q++) CP_ASYNC16(dst + q * 4096, src + q * 4096);
            CP_COMMIT();
        }

        for (int j = 0; j < nt; j++) {
            const int tile = bid + j * GRID;

            // ---- phase 1: raw ready; split raw -> n_h/n_l ----
            CP_WAIT0();
            NAMED_BAR(1, 256);   // raw visible to all; n bufs free (prev epi done)
#pragma unroll
            for (int q = 0; q < 8; q++) {
                int v = u + 256 * q;
                float4 x = ((const float4*)raw)[v];
                __nv_bfloat16 h0, l0, h1, l1, h2, l2, h3, l3;
                bf16_split(x.x, h0, l0);
                bf16_split(x.y, h1, l1);
                bf16_split(x.z, h2, l2);
                bf16_split(x.w, h3, l3);
                int fidx = v * 4;
                int r = fidx >> 7, c = fidx & 127;
                *(uint2*)(n_h + r * A_LDA + c) =
                    make_uint2(pack2(h0, h1), pack2(h2, h3));
                *(uint2*)(n_l + r * A_LDA + c) =
                    make_uint2(pack2(l0, l1), pack2(l2, l3));
            }
            NAMED_BAR(1, 256);   // split done: n bufs ready, raw free

            // issue next tile's cp.async; overlaps mma + epilogue below
            if (j + 1 < nt) {
                const char* src =
                    (const char*)(nfn + (size_t)(bid + (size_t)(j + 1) * GRID) * 8192) +
                    u * 16;
                uint32_t dst = raw_smb + u * 16;
#pragma unroll
                for (int q = 0; q < 8; q++)
                    CP_ASYNC16(dst + q * 4096, src + q * 4096);
                CP_COMMIT();
            }

            // ---- phase 2: mma bf16x3, save h A-frags for epilogue ----
            float acc[2][4][4];
#pragma unroll
            for (int mi = 0; mi < 2; mi++)
#pragma unroll
                for (int ni = 0; ni < 4; ni++)
#pragma unroll
                    for (int r = 0; r < 4; r++) acc[mi][ni][r] = 0.f;

            uint32_t nsav[2][2][4];

#pragma unroll
            for (int kk = 0; kk < 8; kk++) {
                uint32_t ah[2][4], al[2][4];
#pragma unroll
                for (int mi = 0; mi < 2; mi++) {
                    const int row = wm * 32 + mi * 16 + lrow;
                    const uint32_t boff =
                        (uint32_t)(row * (A_LDA * 2) + (kk * 16 + lcol) * 2);
                    ldsm4(ah[mi], nh_smb + boff);
                    ldsm4(al[mi], nl_smb + boff);
                }
                if ((kk >> 1) == wn) {
#pragma unroll
                    for (int mi = 0; mi < 2; mi++)
#pragma unroll
                        for (int r = 0; r < 4; r++)
                            nsav[mi][kk & 1][r] = ah[mi][r];
                }
#pragma unroll
                for (int grp = 0; grp < 2; grp++) {
                    uint32_t bh[4], bl[4];
                    const uint32_t boff =
                        (uint32_t)((kk * 16 + lrow) * (A_LDA * 2) +
                                   (wn * 32 + grp * 16 + lcol) * 2);
                    ldsm4t(bh, ah_smb + boff);
                    ldsm4t(bl, al_smb + boff);
#pragma unroll
                    for (int mi = 0; mi < 2; mi++)
#pragma unroll
                        for (int jj = 0; jj < 2; jj++) {
                            float* d = acc[mi][grp * 2 + jj];
                            mma16816(d, ah[mi], bh + 2 * jj);
                            mma16816(d, ah[mi], bl + 2 * jj);
                            mma16816(d, al[mi], bh + 2 * jj);
                        }
                }
            }

            // ---- phase 3: fragment-resident softmax + pooled ----
            {
                float es[8], pl[8];
#pragma unroll
                for (int c = 0; c < 8; c++) { es[c] = 0.f; pl[c] = 0.f; }

#pragma unroll
                for (int mi = 0; mi < 2; mi++)
#pragma unroll
                    for (int hr = 0; hr < 2; hr++) {
                        const int trow = wm * 32 + mi * 16 + qrow + 8 * hr;
#pragma unroll
                        for (int ni = 0; ni < 4; ni++) {
                            const int col = wn * 32 + ni * 8 + qc;
                            float2 hp = upk_bf2(
                                nsav[mi][ni >> 1][hr + 2 * (ni & 1)]);
                            float2 lp = upk_bf2(
                                *(const uint32_t*)(n_l + trow * A_LDA + col));
                            float n0 = hp.x + lp.x, n1 = hp.y + lp.y;
                            float v0 = acc[mi][ni][hr * 2 + 0];
                            float v1 = acc[mi][ni][hr * 2 + 1];
                            v0 = (v0 > 0.f) ? v0 : ALPHA * v0;
                            v1 = (v1 > 0.f) ? v1 : ALPHA * v1;
                            float e0 = __expf(v0), e1 = __expf(v1);
                            es[ni * 2 + 0] += e0;
                            es[ni * 2 + 1] += e1;
                            pl[ni * 2 + 0] += e0 * n0;
                            pl[ni * 2 + 1] += e1 * n1;
                        }
                    }
#pragma unroll
                for (int c = 0; c < 8; c++) {
#pragma unroll
                    for (int m = 4; m <= 16; m <<= 1) {
                        es[c] += __shfl_xor_sync(0xffffffffu, es[c], m);
                        pl[c] += __shfl_xor_sync(0xffffffffu, pl[c], m);
                    }
                }
                if (lane < 4) {
                    float* dst = g_pooled + (size_t)(tile * 2 + wm) * 128 +
                                 wn * 32 + 2 * lane;
#pragma unroll
                    for (int ni = 0; ni < 4; ni++) {
                        float2 v =
                            make_float2(__fdividef(pl[2 * ni], es[2 * ni]),
                                        __fdividef(pl[2 * ni + 1], es[2 * ni + 1]));
                        *(float2*)(dst + ni * 8) = v;
                    }
                }
            }
            // loop-top bar protects n bufs
        }
    } else {
        // ==================== disf pipeline (warps 8-15), 64-row tiles =====
        const int u = tid - 256;
        const int w = u >> 5;
        const int wm = w & 1;          // 32-row block
        const int wn = w >> 1;         // 32-col block
        const int r = u >> 2;          // row 0..63
        const int q = u & 3;           // 16-channel chunk
        const int p = r >> 5;

        const int nt = (NTILES2 - bid + GRID - 1) / GRID;
        for (int j = 0; j < nt; j++) {
            const int tile = bid + j * GRID;
            const int grow = tile * 64 + r;

            // ---- build dgf straight from LDG ----
            {
                const float4* fnp =
                    (const float4*)(fn + (size_t)grow * 64 + q * 16);
                const float4* fp =
                    (const float4*)(f + (size_t)(tile * 2 + p) * 64 + q * 16);
                float pf[16];
                float df2 = 0.f;
#pragma unroll
                for (int i = 0; i < 4; i++) {
                    float4 A = fnp[i], F = fp[i];
                    pf[i * 4 + 0] = F.x - A.x;
                    pf[i * 4 + 1] = F.y - A.y;
                    pf[i * 4 + 2] = F.z - A.z;
                    pf[i * 4 + 3] = F.w - A.w;
                    float t0 = F.x - 2.f * A.x, t1 = F.y - 2.f * A.y;
                    float t2 = F.z - 2.f * A.z, t3 = F.w - 2.f * A.w;
                    df2 += t0 * t0 + t1 * t1 + t2 * t2 + t3 * t3;
                }
                uint4* dsth = (uint4*)(dgh + r * D_LDG + q * 16);
                uint4* dstl = (uint4*)(dgl + r * D_LDG + q * 16);
                uint32_t hh[8], ll[8];
#pragma unroll
                for (int i = 0; i < 8; i++) {
                    __nv_bfloat16 h0, l0, h1, l1;
                    bf16_split(pf[2 * i], h0, l0);
                    bf16_split(pf[2 * i + 1], h1, l1);
                    hh[i] = pack2(h0, h1);
                    ll[i] = pack2(l0, l1);
                }
                dsth[0] = make_uint4(hh[0], hh[1], hh[2], hh[3]);
                dsth[1] = make_uint4(hh[4], hh[5], hh[6], hh[7]);
                dstl[0] = make_uint4(ll[0], ll[1], ll[2], ll[3]);
                dstl[1] = make_uint4(ll[4], ll[5], ll[6], ll[7]);

                df2 += __shfl_xor_sync(0xffffffffu, df2, 1);
                df2 += __shfl_xor_sync(0xffffffffu, df2, 2);

                if (q == 0) {
                    float tail[16];
#pragma unroll
                    for (int i = 0; i < 16; i++) tail[i] = 0.f;
                    float dg2 = 0.f;
#pragma unroll
                    for (int c = 0; c < 3; c++) {
                        float gv = g[(size_t)(tile * 2 + p) * 3 + c];
                        float gnv = gn[(size_t)grow * 3 + c];
                        tail[c] = gv - gnv;
                        float t = gv - 2.f * gnv;
                        dg2 += t * t;
                    }
                    tail[3] = sqrtf(dg2);
                    tail[4] = sqrtf(df2);
                    tail[5] = 1.0f;
                    uint32_t th[8], tl[8];
#pragma unroll
                    for (int i = 0; i < 8; i++) {
                        __nv_bfloat16 h0, l0, h1, l1;
                        bf16_split(tail[2 * i], h0, l0);
                        bf16_split(tail[2 * i + 1], h1, l1);
                        th[i] = pack2(h0, h1);
                        tl[i] = pack2(l0, l1);
                    }
                    uint4* dh = (uint4*)(dgh + r * D_LDG + 64);
                    uint4* dl = (uint4*)(dgl + r * D_LDG + 64);
                    dh[0] = make_uint4(th[0], th[1], th[2], th[3]);
                    dh[1] = make_uint4(th[4], th[5], th[6], th[7]);
                    dl[0] = make_uint4(tl[0], tl[1], tl[2], tl[3]);
                    dl[1] = make_uint4(tl[4], tl[5], tl[6], tl[7]);
                }
            }
            NAMED_BAR(2, 256);

            // ---- wmma bf16x3 (K=80), 32x32 warp tiles, store to gmem ----
            {
                wmma::fragment<wmma::accumulator, 16, 16, 16, float> acc[2][2];
#pragma unroll
                for (int mi = 0; mi < 2; mi++)
#pragma unroll
                    for (int ni = 0; ni < 2; ni++)
                        wmma::fill_fragment(acc[mi][ni], 0.0f);
#pragma unroll
                for (int kk = 0; kk < 5; kk++) {
                    wmma::fragment<wmma::matrix_a, 16, 16, 16, __nv_bfloat16,
                                   wmma::row_major> dh[2], dl[2];
#pragma unroll
                    for (int mi = 0; mi < 2; mi++) {
                        const int row = wm * 32 + mi * 16;
                        wmma::load_matrix_sync(dh[mi],
                            dgh + row * D_LDG + kk * 16, D_LDG);
                        wmma::load_matrix_sync(dl[mi],
                            dgl + row * D_LDG + kk * 16, D_LDG);
                    }
#pragma unroll
                    for (int ni = 0; ni < 2; ni++) {
                        wmma::fragment<wmma::matrix_b, 16, 16, 16, __nv_bfloat16,
                                       wmma::row_major> wh, wl;
                        const int col = wn * 32 + ni * 16;
                        wmma::load_matrix_sync(wh,
                            w2h + kk * 16 * D_LDW + col, D_LDW);
                        wmma::load_matrix_sync(wl,
                            w2l + kk * 16 * D_LDW + col, D_LDW);
#pragma unroll
                        for (int mi = 0; mi < 2; mi++) {
                            wmma::mma_sync(acc[mi][ni], dh[mi], wh, acc[mi][ni]);
                            wmma::mma_sync(acc[mi][ni], dh[mi], wl, acc[mi][ni]);
                            wmma::mma_sync(acc[mi][ni], dl[mi], wh, acc[mi][ni]);
                        }
                    }
                }
                float* dst = disf + (size_t)tile * 64 * 128;
#pragma unroll
                for (int mi = 0; mi < 2; mi++)
#pragma unroll
                    for (int ni = 0; ni < 2; ni++)
                        wmma::store_matrix_sync(
                            dst + (wm * 32 + mi * 16) * 128 + wn * 32 + ni * 16,
                            acc[mi][ni], 128, wmma::mem_row_major);
            }
            NAMED_BAR(2, 256);
        }
    }
}

// ============================================================================
// out = pooled @ w1 + b1 via wmma bf16x3 (unchanged).
// ============================================================================
#define O_LDW 136
#define O_LDE 132
#define OT_WH 0
#define OT_WL 34816
#define OT_B1 69632
#define OT_PH 70144
#define OT_PL 87552
#define OT_ES 104960
#define SMEM_OUT 138752

__global__ void __launch_bounds__(256, 1)
out_wmma_kernel(const float* __restrict__ w1, const float* __restrict__ b1,
                float* __restrict__ out) {
    extern __shared__ char sm[];
    __nv_bfloat16* w1h = (__nv_bfloat16*)(sm + OT_WH);
    __nv_bfloat16* w1l = (__nv_bfloat16*)(sm + OT_WL);
    float* b1s = (float*)(sm + OT_B1);
    __nv_bfloat16* p_h = (__nv_bfloat16*)(sm + OT_PH);
    __nv_bfloat16* p_l = (__nv_bfloat16*)(sm + OT_PL);
    float* e_s = (float*)(sm + OT_ES);

    const int tid = threadIdx.x;
    const int w = tid >> 5;
    const int wm = w & 1;
    const int wn = w >> 1;

    for (int idx = tid; idx < 128 * 128; idx += 256) {
        int j = idx >> 7, d = idx & 127;
        __nv_bfloat16 h, l;
        bf16_split(w1[idx], h, l);
        w1h[j * O_LDW + d] = h;
        w1l[j * O_LDW + d] = l;
    }
    if (tid < 128) b1s[tid] = b1[tid];
    __syncthreads();

    for (int tile = blockIdx.x; tile < NPTS / 64; tile += GRID) {
        const float4* gsrc = (const float4*)(g_pooled + (size_t)tile * 8192);
#pragma unroll
        for (int q = 0; q < 8; q++) {
            int v = tid + 256 * q;
            float4 x = gsrc[v];
            __nv_bfloat16 h0, l0, h1, l1, h2, l2, h3, l3;
            bf16_split(x.x, h0, l0);
            bf16_split(x.y, h1, l1);
            bf16_split(x.z, h2, l2);
            bf16_split(x.w, h3, l3);
            int fidx = v * 4;
            int r = fidx >> 7, c = fidx & 127;
            *(uint2*)(p_h + r * O_LDW + c) = make_uint2(pack2(h0, h1), pack2(h2, h3));
            *(uint2*)(p_l + r * O_LDW + c) = make_uint2(pack2(l0, l1), pack2(l2, l3));
        }
        __syncthreads();

        {
            wmma::fragment<wmma::accumulator, 16, 16, 16, float> acc[2][2];
#pragma unroll
            for (int mi = 0; mi < 2; mi++)
#pragma unroll
                for (int ni = 0; ni < 2; ni++)
                    wmma::fill_fragment(acc[mi][ni], 0.0f);
#pragma unroll
            for (int kk = 0; kk < 8; kk++) {
                wmma::fragment<wmma::matrix_a, 16, 16, 16, __nv_bfloat16,
                               wmma::row_major> ph[2], pl[2];
                wmma::fragment<wmma::matrix_b, 16, 16, 16, __nv_bfloat16,
                               wmma::row_major> wh[2], wl[2];
#pragma unroll
                for (int mi = 0; mi < 2; mi++) {
                    const int row = wm * 32 + mi * 16;
                    wmma::load_matrix_sync(ph[mi], p_h + row * O_LDW + kk * 16, O_LDW);
                    wmma::load_matrix_sync(pl[mi], p_l + row * O_LDW + kk * 16, O_LDW);
                }
#pragma unroll
                for (int ni = 0; ni < 2; ni++) {
                    const int col = wn * 32 + ni * 16;
                    wmma::load_matrix_sync(wh[ni], w1h + kk * 16 * O_LDW + col, O_LDW);
                    wmma::load_matrix_sync(wl[ni], w1l + kk * 16 * O_LDW + col, O_LDW);
                }
#pragma unroll
                for (int mi = 0; mi < 2; mi++)
#pragma unroll
                    for (int ni = 0; ni < 2; ni++) {
                        wmma::mma_sync(acc[mi][ni], ph[mi], wh[ni], acc[mi][ni]);
                        wmma::mma_sync(acc[mi][ni], ph[mi], wl[ni], acc[mi][ni]);
                        wmma::mma_sync(acc[mi][ni], pl[mi], wh[ni], acc[mi][ni]);
                    }
            }
#pragma unroll
            for (int mi = 0; mi < 2; mi++)
#pragma unroll
                for (int ni = 0; ni < 2; ni++)
                    wmma::store_matrix_sync(
                        e_s + (wm * 32 + mi * 16) * O_LDE + wn * 32 + ni * 16,
                        acc[mi][ni], O_LDE, wmma::mem_row_major);
        }
        __syncthreads();

        {
            float* dst = out + (size_t)tile * 8192;
#pragma unroll
            for (int i = 0; i < 8; i++) {
                int v = tid + 256 * i;
                int rr = v >> 5, c4 = v & 31;
                float4 e4 = *(const float4*)(e_s + rr * O_LDE + c4 * 4);
                float4 b4 = *(const float4*)(b1s + c4 * 4);
                e4.x += b4.x; e4.y += b4.y; e4.z += b4.z; e4.w += b4.w;
                ((float4*)dst)[v] = e4;
            }
        }
        __syncthreads();
    }
}

// ============================================================================
// launch
// ============================================================================
extern "C" void kernel_launch(void* const* d_in, const int* in_sizes, int n_in,
                              void* d_out, int out_size) {
    const float* g = (const float*)d_in[0];
    const float* f = (const float*)d_in[1];
    const float* gn = (const float*)d_in[2];
    const float* fn = (const float*)d_in[3];
    const float* nfn = (const float*)d_in[4];
    const float* a = (const float*)d_in[5];
    const float* w2 = (const float*)d_in[6];
    const float* b2 = (const float*)d_in[7];
    const float* w1 = (const float*)d_in[8];
    const float* b1 = (const float*)d_in[9];

    float* out = (float*)d_out;
    float* disf = out + (size_t)NPTS * DP;

    cudaFuncSetAttribute(fused_kernel,
                         cudaFuncAttributeMaxDynamicSharedMemorySize, SMEM_FUSED);
    cudaFuncSetAttribute(out_wmma_kernel,
                         cudaFuncAttributeMaxDynamicSharedMemorySize, SMEM_OUT);

    fused_kernel<<<GRID, 512, SMEM_FUSED>>>(nfn, a, g, f, gn, fn, w2, b2, disf);
    out_wmma_kernel<<<GRID, 256, SMEM_OUT>>>(w1, b1, out);
}